// round 1
// baseline (speedup 1.0000x reference)
#include <cuda_runtime.h>
#include <cstdint>

// Window attention: B_=4096 windows, N=64 tokens, C=256, H=8 heads, D=32.
// Inputs (metadata order): x[4096,64,256], mask[64,64,64], w_qkv[256,768],
// b_qkv[768], w_proj[256,256], b_proj[256], bias_table[127,8]. Output fp32 [4096,64,256].

#define NWIN   4096
#define NTOK   64
#define CDIM   256
#define NHEAD  8
#define HDIM   32
#define SCALEF 0.17677669529663687f   // 32^-0.5

// Scratch: attention output before projection (256 MB).
__device__ float g_O[(size_t)NWIN * NTOK * CDIM];

// ---------------------------------------------------------------------------
// Kernel A: per-window fused QKV projection + multi-head attention.
// 1 CTA per window, 256 threads.
// Smem (floats): sX 16384 | sK 16384 | sV 16384 | sQt 32*65 | sKt 32*65 | sS 64*65
// sS doubles as the W-chunk staging buffer (16*256 = 4096 <= 4160).
// ---------------------------------------------------------------------------
#define SMEM_A_FLOATS (16384*3 + 2080*2 + 4160)   // 57472 floats = 229888 B

__global__ void __launch_bounds__(256, 1) wattn_qkv_attn(
    const float* __restrict__ x,
    const float* __restrict__ mask,
    const float* __restrict__ wqkv,
    const float* __restrict__ bqkv,
    const float* __restrict__ bias_table)
{
    extern __shared__ float sm[];
    float* sX  = sm;            // [64][256]
    float* sK  = sm + 16384;    // [64][256]
    float* sV  = sm + 32768;    // [64][256]
    float* sQt = sm + 49152;    // [32][65]
    float* sKt = sm + 51232;    // [32][65]
    float* sS  = sm + 53312;    // [64][65]  (also W staging)

    const int b  = blockIdx.x;
    const int t  = threadIdx.x;
    const int tr = t >> 5;      // 0..7  (row group of 8)
    const int tc = t & 31;      // 0..31 (col group of 8 / head-dim lane)

    // ---- load X (64x256) ----
    {
        const float4* src = (const float4*)(x + (size_t)b * (NTOK * CDIM));
        float4* dst = (float4*)sX;
        #pragma unroll
        for (int i = 0; i < 16; i++) dst[t + i * 256] = src[t + i * 256];
    }

    // ---- K and V GEMMs: [64,256] = X @ Wkv + b ----
    for (int kv = 0; kv < 2; kv++) {
        float acc[8][8];
        #pragma unroll
        for (int i = 0; i < 8; i++)
            #pragma unroll
            for (int j = 0; j < 8; j++) acc[i][j] = 0.0f;

        const int colbase = CDIM + kv * CDIM;   // 256 (K) or 512 (V)
        for (int c0 = 0; c0 < CDIM; c0 += 16) {
            __syncthreads();   // protects sS (prev chunk / prev phase), and sX on 1st iter
            #pragma unroll
            for (int v = 0; v < 4; v++) {
                int f = t + v * 256;             // float4 index 0..1023
                int row = f >> 6, col4 = f & 63;
                ((float4*)sS)[row * 64 + col4] =
                    ((const float4*)(wqkv + (size_t)(c0 + row) * 768 + colbase))[col4];
            }
            __syncthreads();
            #pragma unroll
            for (int cc = 0; cc < 16; cc++) {
                float xv[8], wv[8];
                #pragma unroll
                for (int i = 0; i < 8; i++) xv[i] = sX[(tr * 8 + i) * 256 + c0 + cc];
                float4 w0 = ((float4*)sS)[cc * 64 + tc * 2];
                float4 w1 = ((float4*)sS)[cc * 64 + tc * 2 + 1];
                wv[0]=w0.x; wv[1]=w0.y; wv[2]=w0.z; wv[3]=w0.w;
                wv[4]=w1.x; wv[5]=w1.y; wv[6]=w1.z; wv[7]=w1.w;
                #pragma unroll
                for (int i = 0; i < 8; i++)
                    #pragma unroll
                    for (int j = 0; j < 8; j++)
                        acc[i][j] = fmaf(xv[i], wv[j], acc[i][j]);
            }
        }
        __syncthreads();
        float* dstp = kv ? sV : sK;
        float bj[8];
        #pragma unroll
        for (int j = 0; j < 8; j++) bj[j] = bqkv[colbase + tc * 8 + j];
        #pragma unroll
        for (int i = 0; i < 8; i++) {
            float4 o0, o1;
            o0.x = acc[i][0] + bj[0]; o0.y = acc[i][1] + bj[1];
            o0.z = acc[i][2] + bj[2]; o0.w = acc[i][3] + bj[3];
            o1.x = acc[i][4] + bj[4]; o1.y = acc[i][5] + bj[5];
            o1.z = acc[i][6] + bj[6]; o1.w = acc[i][7] + bj[7];
            ((float4*)dstp)[((tr * 8 + i) * 256 + tc * 8) >> 2]     = o0;
            ((float4*)dstp)[((tr * 8 + i) * 256 + tc * 8) >> 2 + 0] = o0; // (kept single path below)
        }
        // NOTE: the duplicated store above would be wrong; do explicit correct stores:
        #pragma unroll
        for (int i = 0; i < 8; i++) {
            #pragma unroll
            for (int j = 0; j < 8; j++)
                dstp[(tr * 8 + i) * 256 + tc * 8 + j] = acc[i][j] + bj[j];
        }
        __syncthreads();
    }

    // ---- per-head attention ----
    for (int h = 0; h < NHEAD; h++) {
        // Q_h = X @ Wq[:, h*32:(h+1)*32]  (recomputed per head; same total cost)
        float qacc[8];
        #pragma unroll
        for (int i = 0; i < 8; i++) qacc[i] = 0.0f;

        for (int c0 = 0; c0 < CDIM; c0 += 16) {
            __syncthreads();   // protects sS (prev head's probabilities / prev chunk)
            #pragma unroll
            for (int v = 0; v < 2; v++) {
                int f = t + v * 256;
                int row = f >> 5, col = f & 31;
                sS[row * 32 + col] = wqkv[(size_t)(c0 + row) * 768 + h * 32 + col];
            }
            __syncthreads();
            #pragma unroll
            for (int cc = 0; cc < 16; cc++) {
                float wq = sS[cc * 32 + tc];
                #pragma unroll
                for (int i = 0; i < 8; i++)
                    qacc[i] = fmaf(sX[(tr * 8 + i) * 256 + c0 + cc], wq, qacc[i]);
            }
        }
        __syncthreads();
        {
            float bq = bqkv[h * 32 + tc];
            #pragma unroll
            for (int i = 0; i < 8; i++)
                sQt[tc * 65 + tr * 8 + i] = qacc[i] + bq;   // Qt[d][n]
        }
        // Kt[d][m] = K[m][h*32+d]
        #pragma unroll
        for (int k = 0; k < 8; k++) {
            int e = t + k * 256;
            int dd = e & 31, m = e >> 5;
            sKt[dd * 65 + m] = sK[m * 256 + h * 32 + dd];
        }
        __syncthreads();

        // S = scale * Qh @ Kh^T + bias + mask, then row softmax.
        // Thread (tn,tm) owns a 4x4 tile; one row spans 16 contiguous lanes (half warp).
        const int tn = t >> 4, tm = t & 15;
        float sacc[4][4];
        #pragma unroll
        for (int i = 0; i < 4; i++)
            #pragma unroll
            for (int j = 0; j < 4; j++) sacc[i][j] = 0.0f;

        #pragma unroll 4
        for (int dd = 0; dd < 32; dd++) {
            float qv[4], kvv[4];
            #pragma unroll
            for (int i = 0; i < 4; i++) qv[i]  = sQt[dd * 65 + tn * 4 + i];
            #pragma unroll
            for (int j = 0; j < 4; j++) kvv[j] = sKt[dd * 65 + tm * 4 + j];
            #pragma unroll
            for (int i = 0; i < 4; i++)
                #pragma unroll
                for (int j = 0; j < 4; j++)
                    sacc[i][j] = fmaf(qv[i], kvv[j], sacc[i][j]);
        }

        const float* mrow = mask + (size_t)(b & 63) * (NTOK * NTOK);
        float p[4][4], rmax[4], rsum[4];
        #pragma unroll
        for (int i = 0; i < 4; i++) {
            int n = tn * 4 + i;
            float mx = -1e30f;
            #pragma unroll
            for (int j = 0; j < 4; j++) {
                int m = tm * 4 + j;
                float s = sacc[i][j] * SCALEF
                        + __ldg(&bias_table[(n - m + 63) * NHEAD + h])
                        + __ldg(&mrow[n * 64 + m]);
                p[i][j] = s;
                mx = fmaxf(mx, s);
            }
            rmax[i] = mx;
        }
        #pragma unroll
        for (int o = 8; o >= 1; o >>= 1)
            #pragma unroll
            for (int i = 0; i < 4; i++)
                rmax[i] = fmaxf(rmax[i], __shfl_xor_sync(0xffffffffu, rmax[i], o));
        #pragma unroll
        for (int i = 0; i < 4; i++) {
            float s = 0.0f;
            #pragma unroll
            for (int j = 0; j < 4; j++) { p[i][j] = __expf(p[i][j] - rmax[i]); s += p[i][j]; }
            rsum[i] = s;
        }
        #pragma unroll
        for (int o = 8; o >= 1; o >>= 1)
            #pragma unroll
            for (int i = 0; i < 4; i++)
                rsum[i] += __shfl_xor_sync(0xffffffffu, rsum[i], o);
        #pragma unroll
        for (int i = 0; i < 4; i++) {
            float inv = 1.0f / rsum[i];
            #pragma unroll
            for (int j = 0; j < 4; j++)
                sS[(tn * 4 + i) * 65 + tm * 4 + j] = p[i][j] * inv;
        }
        __syncthreads();

        // O_h = P @ V_h  -> global scratch
        float oacc[8];
        #pragma unroll
        for (int i = 0; i < 8; i++) oacc[i] = 0.0f;
        #pragma unroll 4
        for (int m = 0; m < 64; m++) {
            float vv = sV[m * 256 + h * 32 + tc];
            #pragma unroll
            for (int i = 0; i < 8; i++)
                oacc[i] = fmaf(sS[(tr * 8 + i) * 65 + m], vv, oacc[i]);
        }
        float* oG = g_O + (size_t)b * (NTOK * CDIM);
        #pragma unroll
        for (int i = 0; i < 8; i++)
            oG[(tr * 8 + i) * 256 + h * 32 + tc] = oacc[i];
        // next head's staging __syncthreads protects sS/sQt/sKt reuse
    }
}

// ---------------------------------------------------------------------------
// Kernel B: output projection. out = O @ Wp + bp, per-window 64x256 GEMM.
// ---------------------------------------------------------------------------
#define SMEM_B_FLOATS (16384 + 4096)   // 81920 B

__global__ void __launch_bounds__(256, 2) wattn_proj(
    const float* __restrict__ wproj,
    const float* __restrict__ bproj,
    float* __restrict__ out)
{
    extern __shared__ float sm[];
    float* sO = sm;            // [64][256]
    float* sW = sm + 16384;    // [16][256] staging

    const int b  = blockIdx.x;
    const int t  = threadIdx.x;
    const int tr = t >> 5;
    const int tc = t & 31;

    {
        const float4* src = (const float4*)(g_O + (size_t)b * (NTOK * CDIM));
        float4* dst = (float4*)sO;
        #pragma unroll
        for (int i = 0; i < 16; i++) dst[t + i * 256] = src[t + i * 256];
    }

    float acc[8][8];
    #pragma unroll
    for (int i = 0; i < 8; i++)
        #pragma unroll
        for (int j = 0; j < 8; j++) acc[i][j] = 0.0f;

    for (int c0 = 0; c0 < CDIM; c0 += 16) {
        __syncthreads();
        #pragma unroll
        for (int v = 0; v < 4; v++) {
            int f = t + v * 256;
            int row = f >> 6, col4 = f & 63;
            ((float4*)sW)[row * 64 + col4] =
                ((const float4*)(wproj + (size_t)(c0 + row) * 256))[col4];
        }
        __syncthreads();
        #pragma unroll
        for (int cc = 0; cc < 16; cc++) {
            float xv[8], wv[8];
            #pragma unroll
            for (int i = 0; i < 8; i++) xv[i] = sO[(tr * 8 + i) * 256 + c0 + cc];
            float4 w0 = ((float4*)sW)[cc * 64 + tc * 2];
            float4 w1 = ((float4*)sW)[cc * 64 + tc * 2 + 1];
            wv[0]=w0.x; wv[1]=w0.y; wv[2]=w0.z; wv[3]=w0.w;
            wv[4]=w1.x; wv[5]=w1.y; wv[6]=w1.z; wv[7]=w1.w;
            #pragma unroll
            for (int i = 0; i < 8; i++)
                #pragma unroll
                for (int j = 0; j < 8; j++)
                    acc[i][j] = fmaf(xv[i], wv[j], acc[i][j]);
        }
    }

    float bj[8];
    #pragma unroll
    for (int j = 0; j < 8; j++) bj[j] = bproj[tc * 8 + j];
    float* orow = out + (size_t)b * (NTOK * CDIM);
    #pragma unroll
    for (int i = 0; i < 8; i++) {
        float4 o0, o1;
        o0.x = acc[i][0] + bj[0]; o0.y = acc[i][1] + bj[1];
        o0.z = acc[i][2] + bj[2]; o0.w = acc[i][3] + bj[3];
        o1.x = acc[i][4] + bj[4]; o1.y = acc[i][5] + bj[5];
        o1.z = acc[i][6] + bj[6]; o1.w = acc[i][7] + bj[7];
        float4* dst = (float4*)(orow + (tr * 8 + i) * 256 + tc * 8);
        dst[0] = o0;
        dst[1] = o1;
    }
}

// ---------------------------------------------------------------------------
extern "C" void kernel_launch(void* const* d_in, const int* in_sizes, int n_in,
                              void* d_out, int out_size)
{
    const float* x          = (const float*)d_in[0];
    const float* mask       = (const float*)d_in[1];
    const float* wqkv       = (const float*)d_in[2];
    const float* bqkv       = (const float*)d_in[3];
    const float* wproj      = (const float*)d_in[4];
    const float* bproj      = (const float*)d_in[5];
    const float* bias_table = (const float*)d_in[6];

    (void)in_sizes; (void)n_in; (void)out_size;

    cudaFuncSetAttribute(wattn_qkv_attn,
                         cudaFuncAttributeMaxDynamicSharedMemorySize,
                         SMEM_A_FLOATS * 4);
    cudaFuncSetAttribute(wattn_proj,
                         cudaFuncAttributeMaxDynamicSharedMemorySize,
                         SMEM_B_FLOATS * 4);

    wattn_qkv_attn<<<NWIN, 256, SMEM_A_FLOATS * 4>>>(x, mask, wqkv, bqkv, bias_table);
    wattn_proj<<<NWIN, 256, SMEM_B_FLOATS * 4>>>(wproj, bproj, (float*)d_out);
}

// round 4
// speedup vs baseline: 1.7142x; 1.7142x over previous
#include <cuda_runtime.h>
#include <cstdint>

// Window attention: B_=4096 windows, N=64 tok, C=256, H=8 heads, D=32. fp32 I/O.
// Pipeline:
//   t0: transpose+tf32-round w_qkv -> g_WqkvT [768,256], w_proj -> g_WprojT [256,256]
//   k1: mma.sync tf32 GEMM  g_QKV[262144,768] = X[262144,256] @ WqkvT^T + b_qkv
//   k2: fp32 per-window attention (S=QK^T, +bias+mask, softmax, O=P V) -> g_O
//   k3: mma.sync tf32 GEMM  out = g_O @ WprojT^T + b_proj
// NOTE: harness PTX target is compute_103 (no 'a') -> tcgen05 unavailable;
// legacy mma.sync tf32 is the fastest available tensor path.

#define NWIN   4096
#define NTOK   64
#define CDIM   256
#define NHEAD  8
#define SCALEF 0.17677669529663687f

__device__ float g_QKV[(size_t)NWIN * NTOK * 768];
__device__ float g_O  [(size_t)NWIN * NTOK * CDIM];
__device__ float g_WqkvT [768 * 256];
__device__ float g_WprojT[256 * 256];

__device__ __forceinline__ float tf32r(float x) {
    float y; asm("cvt.rna.tf32.f32 %0, %1;" : "=f"(y) : "f"(x)); return y;
}

// m16n8k8 tf32 mma: D += A(16x8,row) * B(8x8,col). A,B as b32 regs (tf32 bits).
__device__ __forceinline__ void mma_tf32(float* d, const uint32_t* a, const uint32_t* b) {
    asm volatile(
        "mma.sync.aligned.m16n8k8.row.col.f32.tf32.tf32.f32 "
        "{%0,%1,%2,%3}, {%4,%5,%6,%7}, {%8,%9}, {%0,%1,%2,%3};"
        : "+f"(d[0]), "+f"(d[1]), "+f"(d[2]), "+f"(d[3])
        : "r"(a[0]), "r"(a[1]), "r"(a[2]), "r"(a[3]), "r"(b[0]), "r"(b[1]));
}

// ---------------------------------------------------------------------------
// Kernel 0: transpose src[256, ncol] -> dst[ncol, 256], tf32-rounded.
// ---------------------------------------------------------------------------
__global__ void transpose_tf32(const float* __restrict__ src, float* __restrict__ dst, int ncol)
{
    __shared__ float tile[32][33];
    const int bx = blockIdx.x, by = blockIdx.y;
    const int tx = threadIdx.x, ty0 = threadIdx.y;
    #pragma unroll
    for (int j = 0; j < 32; j += 8)
        tile[ty0 + j][tx] = src[(size_t)(by * 32 + ty0 + j) * ncol + bx * 32 + tx];
    __syncthreads();
    #pragma unroll
    for (int j = 0; j < 32; j += 8)
        dst[(size_t)(bx * 32 + ty0 + j) * 256 + by * 32 + tx] = tf32r(tile[tx][ty0 + j]);
}

// ---------------------------------------------------------------------------
// Kernel 1/3: mma.sync tf32 GEMM.  C[Mtot, ncols] = A[Mtot,256] @ BT^T + bias.
// BT [ncols,256] row-major (k contiguous) == col-major B for mma ".col".
// CTA: 256 thr = 8 warps (4 m x 2 n). CTA tile 128 x 64. A tile resident.
// ---------------------------------------------------------------------------
#define APAD   260                    // float stride (pad 4 -> conflict-free)
#define SMEM_A_BYTES (128 * APAD * 4) // 133120
#define SMEM_B_BYTES (64 * APAD * 4)  // 66560
#define GEMM_SMEM (SMEM_A_BYTES + SMEM_B_BYTES)

__global__ void __launch_bounds__(256, 1) gemm_tf32(
    const float* __restrict__ A, const float* __restrict__ BT,
    const float* __restrict__ bias, float* __restrict__ C, int ncols)
{
    extern __shared__ float sm[];
    float* sA = sm;                       // [128][APAD]
    float* sB = sm + 128 * APAD;          // [64][APAD]

    const int t = threadIdx.x;
    const int wid = t >> 5, lane = t & 31;
    const int warp_m = wid & 3;           // 0..3 -> 32 rows each
    const int warp_n = wid >> 2;          // 0..1 -> 32 cols each
    const int gid = lane >> 2;            // 0..7
    const int tig = lane & 3;             // 0..3
    const int m0 = blockIdx.x * 128;

    // Load A tile [128,256] resident, tf32-rounded.
    #pragma unroll
    for (int i = 0; i < 32; i++) {
        int f = t + i * 256;              // float4 idx 0..8191
        int r = f >> 6, c4 = f & 63;
        float4 v = __ldg((const float4*)A + (size_t)(m0 + r) * 64 + c4);
        v.x = tf32r(v.x); v.y = tf32r(v.y); v.z = tf32r(v.z); v.w = tf32r(v.w);
        *(float4*)(sA + r * APAD + c4 * 4) = v;
    }

    const int ntiles = ncols >> 6;
    for (int nt = 0; nt < ntiles; nt++) {
        const int n0 = nt << 6;
        __syncthreads();                  // prev compute done; A ready (1st iter)
        #pragma unroll
        for (int i = 0; i < 16; i++) {
            int f = t + i * 256;          // float4 idx 0..4095
            int r = f >> 6, c4 = f & 63;
            float4 v = __ldg((const float4*)BT + (size_t)(n0 + r) * 64 + c4);
            *(float4*)(sB + r * APAD + c4 * 4) = v;
        }
        __syncthreads();

        float acc[2][4][4];
        #pragma unroll
        for (int mt = 0; mt < 2; mt++)
            #pragma unroll
            for (int ntt = 0; ntt < 4; ntt++)
                #pragma unroll
                for (int e = 0; e < 4; e++) acc[mt][ntt][e] = 0.0f;

        #pragma unroll 4
        for (int k0 = 0; k0 < 256; k0 += 8) {
            uint32_t afr[2][4], bfr[4][2];
            #pragma unroll
            for (int mt = 0; mt < 2; mt++) {
                const float* ap = sA + (warp_m * 32 + mt * 16 + gid) * APAD + k0 + tig;
                afr[mt][0] = __float_as_uint(ap[0]);
                afr[mt][1] = __float_as_uint(ap[8 * APAD]);
                afr[mt][2] = __float_as_uint(ap[4]);
                afr[mt][3] = __float_as_uint(ap[8 * APAD + 4]);
            }
            #pragma unroll
            for (int ntt = 0; ntt < 4; ntt++) {
                const float* bp = sB + (warp_n * 32 + ntt * 8 + gid) * APAD + k0 + tig;
                bfr[ntt][0] = __float_as_uint(bp[0]);
                bfr[ntt][1] = __float_as_uint(bp[4]);
            }
            #pragma unroll
            for (int mt = 0; mt < 2; mt++)
                #pragma unroll
                for (int ntt = 0; ntt < 4; ntt++)
                    mma_tf32(acc[mt][ntt], afr[mt], bfr[ntt]);
        }

        // Epilogue: bias add + store (registers -> gmem, no smem touched).
        #pragma unroll
        for (int mt = 0; mt < 2; mt++) {
            const int r = m0 + warp_m * 32 + mt * 16 + gid;
            #pragma unroll
            for (int ntt = 0; ntt < 4; ntt++) {
                const int c = n0 + warp_n * 32 + ntt * 8 + tig * 2;
                float b0 = __ldg(bias + c), b1 = __ldg(bias + c + 1);
                float2 v0 = make_float2(acc[mt][ntt][0] + b0, acc[mt][ntt][1] + b1);
                float2 v1 = make_float2(acc[mt][ntt][2] + b0, acc[mt][ntt][3] + b1);
                *(float2*)(C + (size_t)r * ncols + c)       = v0;
                *(float2*)(C + (size_t)(r + 8) * ncols + c) = v1;
            }
        }
    }
}

// ---------------------------------------------------------------------------
// Kernel 2: fp32 per-window attention on precomputed QKV.
// ---------------------------------------------------------------------------
__global__ void __launch_bounds__(256) wattn(
    const float* __restrict__ qkv, const float* __restrict__ mask,
    const float* __restrict__ bias_table, float* __restrict__ O)
{
    __shared__ float sQt[32 * 65];
    __shared__ float sKt[32 * 65];
    __shared__ float sVh[64 * 32];
    __shared__ float sS [64 * 65];

    const int b = blockIdx.x;
    const int t = threadIdx.x;
    const int tr = t >> 5, tc = t & 31;
    const int tn = t >> 4, tm = t & 15;
    const float* base = qkv + (size_t)b * (64 * 768);
    const float* mrow = mask + (size_t)(b & 63) * 4096;

    for (int h = 0; h < NHEAD; h++) {
        __syncthreads();
        #pragma unroll
        for (int i = 0; i < 8; i++) {
            int f = t + i * 256;
            int n = f >> 5, dd = f & 31;
            const float* rowp = base + n * 768 + h * 32 + dd;
            sQt[dd * 65 + n] = rowp[0];
            sKt[dd * 65 + n] = rowp[256];
            sVh[n * 32 + dd] = rowp[512];
        }
        __syncthreads();

        float sacc[4][4];
        #pragma unroll
        for (int i = 0; i < 4; i++)
            #pragma unroll
            for (int j = 0; j < 4; j++) sacc[i][j] = 0.0f;
        #pragma unroll 4
        for (int dd = 0; dd < 32; dd++) {
            float qv[4], kv[4];
            #pragma unroll
            for (int i = 0; i < 4; i++) qv[i] = sQt[dd * 65 + tn * 4 + i];
            #pragma unroll
            for (int j = 0; j < 4; j++) kv[j] = sKt[dd * 65 + tm * 4 + j];
            #pragma unroll
            for (int i = 0; i < 4; i++)
                #pragma unroll
                for (int j = 0; j < 4; j++)
                    sacc[i][j] = fmaf(qv[i], kv[j], sacc[i][j]);
        }

        float p[4][4], rmax[4], rsum[4];
        #pragma unroll
        for (int i = 0; i < 4; i++) {
            int n = tn * 4 + i;
            float mx = -1e30f;
            #pragma unroll
            for (int j = 0; j < 4; j++) {
                int m = tm * 4 + j;
                float s = sacc[i][j] * SCALEF
                        + __ldg(&bias_table[(n - m + 63) * NHEAD + h])
                        + __ldg(&mrow[n * 64 + m]);
                p[i][j] = s;
                mx = fmaxf(mx, s);
            }
            rmax[i] = mx;
        }
        #pragma unroll
        for (int o = 8; o >= 1; o >>= 1)
            #pragma unroll
            for (int i = 0; i < 4; i++)
                rmax[i] = fmaxf(rmax[i], __shfl_xor_sync(0xffffffffu, rmax[i], o));
        #pragma unroll
        for (int i = 0; i < 4; i++) {
            float s = 0.0f;
            #pragma unroll
            for (int j = 0; j < 4; j++) { p[i][j] = __expf(p[i][j] - rmax[i]); s += p[i][j]; }
            rsum[i] = s;
        }
        #pragma unroll
        for (int o = 8; o >= 1; o >>= 1)
            #pragma unroll
            for (int i = 0; i < 4; i++)
                rsum[i] += __shfl_xor_sync(0xffffffffu, rsum[i], o);
        #pragma unroll
        for (int i = 0; i < 4; i++) {
            float inv = 1.0f / rsum[i];
            #pragma unroll
            for (int j = 0; j < 4; j++)
                sS[(tn * 4 + i) * 65 + tm * 4 + j] = p[i][j] * inv;
        }
        __syncthreads();

        float oacc[8];
        #pragma unroll
        for (int i = 0; i < 8; i++) oacc[i] = 0.0f;
        #pragma unroll 4
        for (int m = 0; m < 64; m++) {
            float vv = sVh[m * 32 + tc];
            #pragma unroll
            for (int i = 0; i < 8; i++)
                oacc[i] = fmaf(sS[(tr * 8 + i) * 65 + m], vv, oacc[i]);
        }
        float* og = O + (size_t)b * (64 * 256);
        #pragma unroll
        for (int i = 0; i < 8; i++)
            og[(tr * 8 + i) * 256 + h * 32 + tc] = oacc[i];
    }
}

// ---------------------------------------------------------------------------
extern "C" void kernel_launch(void* const* d_in, const int* in_sizes, int n_in,
                              void* d_out, int out_size)
{
    const float* x          = (const float*)d_in[0];
    const float* mask       = (const float*)d_in[1];
    const float* wqkv       = (const float*)d_in[2];
    const float* bqkv       = (const float*)d_in[3];
    const float* wproj      = (const float*)d_in[4];
    const float* bproj      = (const float*)d_in[5];
    const float* bias_table = (const float*)d_in[6];
    (void)in_sizes; (void)n_in; (void)out_size;

    cudaFuncSetAttribute(gemm_tf32, cudaFuncAttributeMaxDynamicSharedMemorySize, GEMM_SMEM);

    float *qkvT, *projT, *qkvS, *oS;
    cudaGetSymbolAddress((void**)&qkvT,  g_WqkvT);
    cudaGetSymbolAddress((void**)&projT, g_WprojT);
    cudaGetSymbolAddress((void**)&qkvS,  g_QKV);
    cudaGetSymbolAddress((void**)&oS,    g_O);

    transpose_tf32<<<dim3(24, 8), dim3(32, 8)>>>(wqkv,  qkvT, 768);
    transpose_tf32<<<dim3(8, 8),  dim3(32, 8)>>>(wproj, projT, 256);
    gemm_tf32<<<2048, 256, GEMM_SMEM>>>(x, qkvT, bqkv, qkvS, 768);
    wattn<<<NWIN, 256>>>(qkvS, mask, bias_table, oS);
    gemm_tf32<<<2048, 256, GEMM_SMEM>>>(oS, projT, bproj, (float*)d_out, 256);
}

// round 5
// speedup vs baseline: 3.1782x; 1.8541x over previous
#include <cuda_runtime.h>
#include <cstdint>

// Window attention: B_=4096 windows, N=64 tok, C=256, H=8 heads, D=32. fp32 I/O.
// Pipeline:
//   r0: g_Xr = tf32-round(x)                      (enables cp.async GEMM, no cvt)
//   t0: transpose+round w_qkv/w_proj -> g_W*T
//   k1: pipelined mma.sync tf32 GEMM  g_QKV = g_Xr @ WqkvT^T + b_qkv
//   k2: fp32 attention (vectorized smem), writes g_O tf32-rounded
//   k3: pipelined GEMM  out = g_O @ WprojT^T + b_proj
// (PTX target compute_103: tcgen05 unavailable; legacy mma.sync tf32 path.)

#define NWIN   4096
#define NTOK   64
#define CDIM   256
#define NHEAD  8
#define SCALEF 0.17677669529663687f

__device__ float g_QKV[(size_t)NWIN * NTOK * 768];
__device__ float g_O  [(size_t)NWIN * NTOK * CDIM];
__device__ float g_Xr [(size_t)NWIN * NTOK * CDIM];
__device__ float g_WqkvT [768 * 256];
__device__ float g_WprojT[256 * 256];

__device__ __forceinline__ float tf32r(float x) {
    float y; asm("cvt.rna.tf32.f32 %0, %1;" : "=f"(y) : "f"(x)); return y;
}
__device__ __forceinline__ uint32_t smem_u32(const void* p) {
    uint32_t a;
    asm("{ .reg .u64 t; cvta.to.shared.u64 t, %1; cvt.u32.u64 %0, t; }" : "=r"(a) : "l"(p));
    return a;
}
__device__ __forceinline__ void cp_async16(uint32_t dst, const void* src) {
    asm volatile("cp.async.cg.shared.global [%0], [%1], 16;" :: "r"(dst), "l"(src));
}
__device__ __forceinline__ void cp_commit() {
    asm volatile("cp.async.commit_group;" ::: "memory");
}
template<int N> __device__ __forceinline__ void cp_wait() {
    asm volatile("cp.async.wait_group %0;" :: "n"(N) : "memory");
}

// m16n8k8 tf32 mma: D += A(16x8,row) * B(8x8,col).
__device__ __forceinline__ void mma_tf32(float* d, const uint32_t* a, const uint32_t* b) {
    asm volatile(
        "mma.sync.aligned.m16n8k8.row.col.f32.tf32.tf32.f32 "
        "{%0,%1,%2,%3}, {%4,%5,%6,%7}, {%8,%9}, {%0,%1,%2,%3};"
        : "+f"(d[0]), "+f"(d[1]), "+f"(d[2]), "+f"(d[3])
        : "r"(a[0]), "r"(a[1]), "r"(a[2]), "r"(a[3]), "r"(b[0]), "r"(b[1]));
}

// ---------------------------------------------------------------------------
// Kernel r0: elementwise tf32 rounding (float4).
// ---------------------------------------------------------------------------
__global__ void round_tf32(const float4* __restrict__ in, float4* __restrict__ out)
{
    int i = blockIdx.x * blockDim.x + threadIdx.x;
    float4 v = in[i];
    v.x = tf32r(v.x); v.y = tf32r(v.y); v.z = tf32r(v.z); v.w = tf32r(v.w);
    out[i] = v;
}

// ---------------------------------------------------------------------------
// Kernel t0: transpose src[256, ncol] -> dst[ncol, 256], tf32-rounded.
// ---------------------------------------------------------------------------
__global__ void transpose_tf32(const float* __restrict__ src, float* __restrict__ dst, int ncol)
{
    __shared__ float tile[32][33];
    const int bx = blockIdx.x, by = blockIdx.y;
    const int tx = threadIdx.x, ty0 = threadIdx.y;
    #pragma unroll
    for (int j = 0; j < 32; j += 8)
        tile[ty0 + j][tx] = src[(size_t)(by * 32 + ty0 + j) * ncol + bx * 32 + tx];
    __syncthreads();
    #pragma unroll
    for (int j = 0; j < 32; j += 8)
        dst[(size_t)(bx * 32 + ty0 + j) * 256 + by * 32 + tx] = tf32r(tile[tx][ty0 + j]);
}

// ---------------------------------------------------------------------------
// Kernel k1/k3: pipelined mma.sync tf32 GEMM.
// C[Mtot, ncols] = A[Mtot,256] @ BT^T + bias.   A, BT pre-rounded to tf32.
// CTA tile 128x128, K chunks of 32, 2-stage cp.async double buffer.
// 256 thr = 8 warps (4m x 2n), warp tile 32x64.
// ---------------------------------------------------------------------------
#define BM 128
#define BN 128
#define BK 32
#define KPAD 36                               // floats per smem row
#define STAGE_FLOATS (BM * KPAD)              // 4608
#define GEMM_SMEM_BYTES (4 * STAGE_FLOATS * 4) // 2 arrays x 2 stages = 73728

__global__ void __launch_bounds__(256, 2) gemm_tf32(
    const float* __restrict__ A, const float* __restrict__ BT,
    const float* __restrict__ bias, float* __restrict__ C, int ncols)
{
    extern __shared__ float sm[];
    float* sA = sm;                       // [2][BM][KPAD]
    float* sB = sm + 2 * STAGE_FLOATS;    // [2][BM][KPAD]

    const int t = threadIdx.x;
    const int wid = t >> 5, lane = t & 31;
    const int wm = wid & 3, wn = wid >> 2;
    const int gid = lane >> 2, tig = lane & 3;
    const int m0 = blockIdx.x * BM;
    const int n0 = blockIdx.y * BN;

    const uint32_t sAu = smem_u32(sA);
    const uint32_t sBu = smem_u32(sB);

    // async-load one K-chunk into stage s
    const int lrow = t >> 3, lc4 = t & 7;           // 32 rows per 256-thr pass? no:
    // each thread: 4 float4 of A and 4 of B per chunk (f = t + i*256)
    auto load_chunk = [&](int kc, int s) {
        #pragma unroll
        for (int i = 0; i < 4; i++) {
            int f = t + i * 256;                    // 0..1023
            int r = f >> 3, c4 = f & 7;
            const float* ga = A + (size_t)(m0 + r) * CDIM + kc * BK + c4 * 4;
            cp_async16(sAu + (uint32_t)(s * STAGE_FLOATS + r * KPAD + c4 * 4) * 4, ga);
        }
        #pragma unroll
        for (int i = 0; i < 4; i++) {
            int f = t + i * 256;
            int r = f >> 3, c4 = f & 7;
            const float* gb = BT + (size_t)(n0 + r) * CDIM + kc * BK + c4 * 4;
            cp_async16(sBu + (uint32_t)(s * STAGE_FLOATS + r * KPAD + c4 * 4) * 4, gb);
        }
    };
    (void)lrow; (void)lc4;

    float acc[2][8][4];
    #pragma unroll
    for (int mt = 0; mt < 2; mt++)
        #pragma unroll
        for (int nt = 0; nt < 8; nt++)
            #pragma unroll
            for (int e = 0; e < 4; e++) acc[mt][nt][e] = 0.0f;

    load_chunk(0, 0);
    cp_commit();

    #pragma unroll 1
    for (int kc = 0; kc < CDIM / BK; kc++) {
        if (kc + 1 < CDIM / BK) load_chunk(kc + 1, (kc + 1) & 1);
        cp_commit();
        cp_wait<1>();
        __syncthreads();

        const float* a_s = sA + (kc & 1) * STAGE_FLOATS;
        const float* b_s = sB + (kc & 1) * STAGE_FLOATS;
        #pragma unroll
        for (int kk = 0; kk < BK; kk += 8) {
            uint32_t af[2][4], bf[8][2];
            #pragma unroll
            for (int mt = 0; mt < 2; mt++) {
                const float* ap = a_s + (wm * 32 + mt * 16 + gid) * KPAD + kk + tig;
                af[mt][0] = __float_as_uint(ap[0]);
                af[mt][1] = __float_as_uint(ap[8 * KPAD]);
                af[mt][2] = __float_as_uint(ap[4]);
                af[mt][3] = __float_as_uint(ap[8 * KPAD + 4]);
            }
            #pragma unroll
            for (int nt = 0; nt < 8; nt++) {
                const float* bp = b_s + (wn * 64 + nt * 8 + gid) * KPAD + kk + tig;
                bf[nt][0] = __float_as_uint(bp[0]);
                bf[nt][1] = __float_as_uint(bp[4]);
            }
            #pragma unroll
            for (int mt = 0; mt < 2; mt++)
                #pragma unroll
                for (int nt = 0; nt < 8; nt++)
                    mma_tf32(acc[mt][nt], af[mt], bf[nt]);
        }
        __syncthreads();
    }

    // Epilogue: bias + store.
    #pragma unroll
    for (int mt = 0; mt < 2; mt++) {
        const int r = m0 + wm * 32 + mt * 16 + gid;
        #pragma unroll
        for (int nt = 0; nt < 8; nt++) {
            const int c = n0 + wn * 64 + nt * 8 + tig * 2;
            float b0 = __ldg(bias + c), b1 = __ldg(bias + c + 1);
            float2 v0 = make_float2(acc[mt][nt][0] + b0, acc[mt][nt][1] + b1);
            float2 v1 = make_float2(acc[mt][nt][2] + b0, acc[mt][nt][3] + b1);
            *(float2*)(C + (size_t)r * ncols + c)       = v0;
            *(float2*)(C + (size_t)(r + 8) * ncols + c) = v1;
        }
    }
}

// ---------------------------------------------------------------------------
// Kernel k2: fp32 per-window attention, vectorized smem layout.
// Q/K/V stored n-major [64][36]; S-GEMM reads float4 along d.
// Thread (tn,tm): rows tn*4+i, cols tm+16j (strided cols -> conflict-free K).
// Output written tf32-rounded (feeds proj GEMM via cp.async).
// ---------------------------------------------------------------------------
#define QPAD 36
#define SPAD 68

__global__ void __launch_bounds__(256) wattn(
    const float* __restrict__ qkv, const float* __restrict__ mask,
    const float* __restrict__ bias_table, float* __restrict__ O)
{
    __shared__ float sQ[64 * QPAD];
    __shared__ float sK[64 * QPAD];
    __shared__ float sV[64 * QPAD];
    __shared__ float sS[64 * SPAD];

    const int b = blockIdx.x;
    const int t = threadIdx.x;
    const int tr = t >> 5, tc = t & 31;
    const int tn = t >> 4, tm = t & 15;
    const float* base = qkv + (size_t)b * (64 * 768);
    const float* mrow = mask + (size_t)(b & 63) * 4096;
    float* og = O + (size_t)b * (64 * 256);

    for (int h = 0; h < NHEAD; h++) {
        __syncthreads();   // previous head's smem reads done
        // load Q/K/V head slices: 512 float4 each, n-major.
        #pragma unroll
        for (int i = 0; i < 2; i++) {
            int f4 = t + i * 256;            // 0..511
            int n = f4 >> 3, quad = f4 & 7;
            const float4* rp = (const float4*)(base + n * 768 + h * 32) + quad;
            *(float4*)&sQ[n * QPAD + quad * 4] = rp[0];
            *(float4*)&sK[n * QPAD + quad * 4] = rp[64];    // +256 floats
            *(float4*)&sV[n * QPAD + quad * 4] = rp[128];   // +512 floats
        }
        __syncthreads();

        // S = scale*QK^T + bias + mask ; rows tn*4+i, cols tm+16j
        float sacc[4][4];
        #pragma unroll
        for (int i = 0; i < 4; i++)
            #pragma unroll
            for (int j = 0; j < 4; j++) sacc[i][j] = 0.0f;

        #pragma unroll
        for (int d0 = 0; d0 < 32; d0 += 4) {
            float4 q4[4], k4[4];
            #pragma unroll
            for (int i = 0; i < 4; i++)
                q4[i] = *(const float4*)&sQ[(tn * 4 + i) * QPAD + d0];
            #pragma unroll
            for (int j = 0; j < 4; j++)
                k4[j] = *(const float4*)&sK[(tm + 16 * j) * QPAD + d0];
            #pragma unroll
            for (int i = 0; i < 4; i++)
                #pragma unroll
                for (int j = 0; j < 4; j++) {
                    sacc[i][j] = fmaf(q4[i].x, k4[j].x, sacc[i][j]);
                    sacc[i][j] = fmaf(q4[i].y, k4[j].y, sacc[i][j]);
                    sacc[i][j] = fmaf(q4[i].z, k4[j].z, sacc[i][j]);
                    sacc[i][j] = fmaf(q4[i].w, k4[j].w, sacc[i][j]);
                }
        }

        float p[4][4], rmax[4], rsum[4];
        #pragma unroll
        for (int i = 0; i < 4; i++) {
            int n = tn * 4 + i;
            float mx = -1e30f;
            #pragma unroll
            for (int j = 0; j < 4; j++) {
                int m = tm + 16 * j;
                float s = sacc[i][j] * SCALEF
                        + __ldg(&bias_table[(n - m + 63) * NHEAD + h])
                        + __ldg(&mrow[n * 64 + m]);
                p[i][j] = s;
                mx = fmaxf(mx, s);
            }
            rmax[i] = mx;
        }
        #pragma unroll
        for (int o = 8; o >= 1; o >>= 1)
            #pragma unroll
            for (int i = 0; i < 4; i++)
                rmax[i] = fmaxf(rmax[i], __shfl_xor_sync(0xffffffffu, rmax[i], o));
        #pragma unroll
        for (int i = 0; i < 4; i++) {
            float s = 0.0f;
            #pragma unroll
            for (int j = 0; j < 4; j++) { p[i][j] = __expf(p[i][j] - rmax[i]); s += p[i][j]; }
            rsum[i] = s;
        }
        #pragma unroll
        for (int o = 8; o >= 1; o >>= 1)
            #pragma unroll
            for (int i = 0; i < 4; i++)
                rsum[i] += __shfl_xor_sync(0xffffffffu, rsum[i], o);
        #pragma unroll
        for (int i = 0; i < 4; i++) {
            float inv = 1.0f / rsum[i];
            #pragma unroll
            for (int j = 0; j < 4; j++)
                sS[(tn * 4 + i) * SPAD + tm + 16 * j] = p[i][j] * inv;
        }
        __syncthreads();

        // O_h = P @ V_h : rows tr*8+i, col tc.
        float oacc[8];
        #pragma unroll
        for (int i = 0; i < 8; i++) oacc[i] = 0.0f;
        #pragma unroll
        for (int m0 = 0; m0 < 64; m0 += 4) {
            float v0 = sV[(m0 + 0) * QPAD + tc];
            float v1 = sV[(m0 + 1) * QPAD + tc];
            float v2 = sV[(m0 + 2) * QPAD + tc];
            float v3 = sV[(m0 + 3) * QPAD + tc];
            #pragma unroll
            for (int i = 0; i < 8; i++) {
                float4 s4 = *(const float4*)&sS[(tr * 8 + i) * SPAD + m0];
                oacc[i] = fmaf(s4.x, v0, oacc[i]);
                oacc[i] = fmaf(s4.y, v1, oacc[i]);
                oacc[i] = fmaf(s4.z, v2, oacc[i]);
                oacc[i] = fmaf(s4.w, v3, oacc[i]);
            }
        }
        #pragma unroll
        for (int i = 0; i < 8; i++)
            og[(tr * 8 + i) * 256 + h * 32 + tc] = tf32r(oacc[i]);
    }
}

// ---------------------------------------------------------------------------
extern "C" void kernel_launch(void* const* d_in, const int* in_sizes, int n_in,
                              void* d_out, int out_size)
{
    const float* x          = (const float*)d_in[0];
    const float* mask       = (const float*)d_in[1];
    const float* wqkv       = (const float*)d_in[2];
    const float* bqkv       = (const float*)d_in[3];
    const float* wproj      = (const float*)d_in[4];
    const float* bproj      = (const float*)d_in[5];
    const float* bias_table = (const float*)d_in[6];
    (void)in_sizes; (void)n_in; (void)out_size;

    cudaFuncSetAttribute(gemm_tf32, cudaFuncAttributeMaxDynamicSharedMemorySize,
                         GEMM_SMEM_BYTES);

    float *qkvT, *projT, *qkvS, *oS, *xr;
    cudaGetSymbolAddress((void**)&qkvT,  g_WqkvT);
    cudaGetSymbolAddress((void**)&projT, g_WprojT);
    cudaGetSymbolAddress((void**)&qkvS,  g_QKV);
    cudaGetSymbolAddress((void**)&oS,    g_O);
    cudaGetSymbolAddress((void**)&xr,    g_Xr);

    // total x elements = 4096*64*256 = 67108864 -> 16777216 float4
    round_tf32<<<65536, 256>>>((const float4*)x, (float4*)xr);
    transpose_tf32<<<dim3(24, 8), dim3(32, 8)>>>(wqkv,  qkvT, 768);
    transpose_tf32<<<dim3(8, 8),  dim3(32, 8)>>>(wproj, projT, 256);
    gemm_tf32<<<dim3(2048, 6), 256, GEMM_SMEM_BYTES>>>(xr, qkvT, bqkv, qkvS, 768);
    wattn<<<NWIN, 256>>>(qkvS, mask, bias_table, oS);
    gemm_tf32<<<dim3(2048, 2), 256, GEMM_SMEM_BYTES>>>(oS, projT, bproj, (float*)d_out, 256);
}

// round 7
// speedup vs baseline: 3.5849x; 1.1280x over previous
#include <cuda_runtime.h>
#include <cstdint>

// Window attention: B_=4096 windows, N=64 tok, C=256, H=8 heads, D=32. fp32 I/O.
//   t0: transpose+round w_qkv/w_proj -> g_W*T (tf32)
//   k1: A-resident N-looped mma.sync tf32 GEMM  g_QKV = x @ WqkvT^T + b_qkv
//   k2: mma.sync tf32 attention (S=QK^T, softmax, O=P V) -> g_O
//   k3: same GEMM  out = g_O @ WprojT^T + b_proj
// (PTX target compute_103: tcgen05 unavailable; legacy mma.sync tf32 path.)

#define NWIN   4096
#define CDIM   256
#define NHEAD  8
#define SCALEF 0.17677669529663687f

__device__ float g_QKV[(size_t)NWIN * 64 * 768];
__device__ float g_O  [(size_t)NWIN * 64 * 256];
__device__ float g_WqkvT [768 * 256];
__device__ float g_WprojT[256 * 256];

__device__ __forceinline__ float tf32r(float x) {
    float y; asm("cvt.rna.tf32.f32 %0, %1;" : "=f"(y) : "f"(x)); return y;
}
__device__ __forceinline__ uint32_t smem_u32(const void* p) {
    uint32_t a;
    asm("{ .reg .u64 t; cvta.to.shared.u64 t, %1; cvt.u32.u64 %0, t; }" : "=r"(a) : "l"(p));
    return a;
}
__device__ __forceinline__ void cp_async16(uint32_t dst, const void* src) {
    asm volatile("cp.async.cg.shared.global [%0], [%1], 16;" :: "r"(dst), "l"(src));
}
__device__ __forceinline__ void cp_commit() {
    asm volatile("cp.async.commit_group;" ::: "memory");
}
template<int N> __device__ __forceinline__ void cp_wait() {
    asm volatile("cp.async.wait_group %0;" :: "n"(N) : "memory");
}

// m16n8k8 tf32 mma: D += A(16x8,row) * B(8x8,col).
__device__ __forceinline__ void mma_tf32(float* d, const uint32_t* a, const uint32_t* b) {
    asm volatile(
        "mma.sync.aligned.m16n8k8.row.col.f32.tf32.tf32.f32 "
        "{%0,%1,%2,%3}, {%4,%5,%6,%7}, {%8,%9}, {%0,%1,%2,%3};"
        : "+f"(d[0]), "+f"(d[1]), "+f"(d[2]), "+f"(d[3])
        : "r"(a[0]), "r"(a[1]), "r"(a[2]), "r"(a[3]), "r"(b[0]), "r"(b[1]));
}

// ---------------------------------------------------------------------------
// Kernel t0: transpose src[256, ncol] -> dst[ncol, 256], tf32-rounded.
// ---------------------------------------------------------------------------
__global__ void transpose_tf32(const float* __restrict__ src, float* __restrict__ dst, int ncol)
{
    __shared__ float tile[32][33];
    const int bx = blockIdx.x, by = blockIdx.y;
    const int tx = threadIdx.x, ty0 = threadIdx.y;
    #pragma unroll
    for (int j = 0; j < 32; j += 8)
        tile[ty0 + j][tx] = src[(size_t)(by * 32 + ty0 + j) * ncol + bx * 32 + tx];
    __syncthreads();
    #pragma unroll
    for (int j = 0; j < 32; j += 8)
        dst[(size_t)(bx * 32 + ty0 + j) * 256 + by * 32 + tx] = tf32r(tile[tx][ty0 + j]);
}

// ---------------------------------------------------------------------------
// Kernel k1/k3: A-resident, N-looped mma.sync tf32 GEMM.
// C[Mtot, ncols] = A[Mtot,256] @ BT^T + bias.  A fp32 (rounded at stage),
// BT [ncols,256] pre-rounded.  CTA: 128 rows resident; loops ncols in
// 128-col tiles; B double-buffered via cp.async in K-chunks of 32.
// 256 thr = 8 warps (4m x 2n), warp tile 32x64.
// ---------------------------------------------------------------------------
#define BM 128
#define BK 32
#define APAD 260
#define BPAD 36
#define BSTAGE (BM * BPAD)                         // 4608 floats
#define GEMM_SMEM ((BM * APAD + 2 * BSTAGE) * 4)   // 169984 B

__global__ void __launch_bounds__(256, 1) gemm_tf32(
    const float* __restrict__ A, const float* __restrict__ BT,
    const float* __restrict__ bias, float* __restrict__ C, int ncols)
{
    extern __shared__ float sm[];
    float* sA = sm;                        // [128][APAD]
    float* sB = sm + BM * APAD;            // [2][128][BPAD]

    const int t = threadIdx.x;
    const int wid = t >> 5, lane = t & 31;
    const int wm = wid & 3, wn = wid >> 2;
    const int gid = lane >> 2, tig = lane & 3;
    const int m0 = blockIdx.x * BM;
    const uint32_t sBu = smem_u32(sB);

    // Stage A resident [128x256], tf32-rounded.
    #pragma unroll
    for (int i = 0; i < 32; i++) {
        int f = t + i * 256;               // float4 idx 0..8191
        int r = f >> 6, c4 = f & 63;
        float4 v = __ldg((const float4*)(A + (size_t)(m0 + r) * CDIM) + c4);
        v.x = tf32r(v.x); v.y = tf32r(v.y); v.z = tf32r(v.z); v.w = tf32r(v.w);
        *(float4*)(sA + r * APAD + c4 * 4) = v;
    }

    auto loadB = [&](int n0, int kc, int s) {
        #pragma unroll
        for (int i = 0; i < 4; i++) {
            int f = t + i * 256;           // 0..1023
            int r = f >> 3, c4 = f & 7;
            cp_async16(sBu + (uint32_t)(s * BSTAGE + r * BPAD + c4 * 4) * 4,
                       BT + (size_t)(n0 + r) * CDIM + kc * BK + c4 * 4);
        }
    };

    const int ntiles = ncols >> 7;
    for (int nt = 0; nt < ntiles; nt++) {
        const int n0 = nt << 7;

        float acc[2][8][4];
        #pragma unroll
        for (int mt = 0; mt < 2; mt++)
            #pragma unroll
            for (int ntt = 0; ntt < 8; ntt++)
                #pragma unroll
                for (int e = 0; e < 4; e++) acc[mt][ntt][e] = 0.0f;

        loadB(n0, 0, 0);
        cp_commit();

        #pragma unroll 1
        for (int kc = 0; kc < CDIM / BK; kc++) {
            if (kc + 1 < CDIM / BK) {
                loadB(n0, kc + 1, (kc + 1) & 1);
                cp_commit();
                cp_wait<1>();
            } else {
                cp_wait<0>();
            }
            __syncthreads();   // chunk kc visible; prev-stage reads done

            const float* b_s = sB + (kc & 1) * BSTAGE;
            #pragma unroll
            for (int kk = 0; kk < BK; kk += 8) {
                uint32_t af[2][4], bf[8][2];
                #pragma unroll
                for (int mt = 0; mt < 2; mt++) {
                    const float* ap = sA + (wm * 32 + mt * 16 + gid) * APAD + kc * BK + kk + tig;
                    af[mt][0] = __float_as_uint(ap[0]);
                    af[mt][1] = __float_as_uint(ap[8 * APAD]);
                    af[mt][2] = __float_as_uint(ap[4]);
                    af[mt][3] = __float_as_uint(ap[8 * APAD + 4]);
                }
                #pragma unroll
                for (int ntt = 0; ntt < 8; ntt++) {
                    const float* bp = b_s + (wn * 64 + ntt * 8 + gid) * BPAD + kk + tig;
                    bf[ntt][0] = __float_as_uint(bp[0]);
                    bf[ntt][1] = __float_as_uint(bp[4]);
                }
                #pragma unroll
                for (int mt = 0; mt < 2; mt++)
                    #pragma unroll
                    for (int ntt = 0; ntt < 8; ntt++)
                        mma_tf32(acc[mt][ntt], af[mt], bf[ntt]);
            }
            __syncthreads();   // stage free for the load 2 chunks ahead
        }

        // Epilogue for this n-tile.
        #pragma unroll
        for (int mt = 0; mt < 2; mt++) {
            const int r = m0 + wm * 32 + mt * 16 + gid;
            #pragma unroll
            for (int ntt = 0; ntt < 8; ntt++) {
                const int c = n0 + wn * 64 + ntt * 8 + tig * 2;
                float b0 = __ldg(bias + c), b1 = __ldg(bias + c + 1);
                float2 v0 = make_float2(acc[mt][ntt][0] + b0, acc[mt][ntt][1] + b1);
                float2 v1 = make_float2(acc[mt][ntt][2] + b0, acc[mt][ntt][3] + b1);
                *(float2*)(C + (size_t)r * ncols + c)       = v0;
                *(float2*)(C + (size_t)(r + 8) * ncols + c) = v1;
            }
        }
    }
}

// ---------------------------------------------------------------------------
// Kernel k2: tensor-core attention.
// 8 warps = 2 warp-groups; wg handles head (hp*2+wg) per iteration hp=0..3.
// Per wg: stage Q,K [64][36] + V^T [32][68] (tf32); S via mma (warp=16x64),
// in-register softmax (+bias+mask, shfl over tig quad), P -> smem [64][68],
// O = P@V via mma -> gmem.
// ---------------------------------------------------------------------------
#define QP 36
#define VP 68
#define PP 68
// float offsets per wg
#define OFF_Q(wg)  ((wg) * 2304)
#define OFF_K(wg)  (4608 + (wg) * 2304)
#define OFF_VT(wg) (9216 + (wg) * 2176)
#define OFF_P(wg)  (13568 + (wg) * 4352)
#define WATTN_SMEM ((13568 + 2 * 4352) * 4)   // 89088 B

__global__ void __launch_bounds__(256) wattn(
    const float* __restrict__ qkv, const float* __restrict__ mask,
    const float* __restrict__ bt, float* __restrict__ O)
{
    extern __shared__ float sm[];
    const int t = threadIdx.x, wid = t >> 5, lane = t & 31;
    const int wg = wid >> 2, wm = wid & 3;
    const int gid = lane >> 2, tig = lane & 3;
    const int tt = t & 127;
    const int b = blockIdx.x;

    float* sQ  = sm + OFF_Q(wg);
    float* sK  = sm + OFF_K(wg);
    float* sVt = sm + OFF_VT(wg);
    float* sP  = sm + OFF_P(wg);

    const float* base = qkv + (size_t)b * (64 * 768);
    const float* mrow = mask + (size_t)(b & 63) * 4096;
    float* og = O + (size_t)b * (64 * 256);

    const int r0 = wm * 16 + gid, r1 = r0 + 8;

    for (int hp = 0; hp < 4; hp++) {
        const int h = hp * 2 + wg;
        __syncthreads();   // previous iteration's smem reads done
        // Stage this wg's head: Q,K row-major [64][QP]; V transposed [32][VP].
        #pragma unroll
        for (int i = 0; i < 4; i++) {
            int u = tt + i * 128;          // 0..511
            int n = u >> 3, q = u & 7;
            const float4* rp = (const float4*)(base + n * 768 + h * 32) + q;
            float4 qa = rp[0];
            qa.x = tf32r(qa.x); qa.y = tf32r(qa.y); qa.z = tf32r(qa.z); qa.w = tf32r(qa.w);
            *(float4*)&sQ[n * QP + q * 4] = qa;
            float4 ka = rp[64];            // +256 floats
            ka.x = tf32r(ka.x); ka.y = tf32r(ka.y); ka.z = tf32r(ka.z); ka.w = tf32r(ka.w);
            *(float4*)&sK[n * QP + q * 4] = ka;
            float4 va = rp[128];           // +512 floats
            sVt[(q * 4 + 0) * VP + n] = tf32r(va.x);
            sVt[(q * 4 + 1) * VP + n] = tf32r(va.y);
            sVt[(q * 4 + 2) * VP + n] = tf32r(va.z);
            sVt[(q * 4 + 3) * VP + n] = tf32r(va.w);
        }
        __syncthreads();

        // S = Q K^T : warp covers rows wm*16..+15, all 64 cols (8 n-tiles).
        float sacc[8][4];
        #pragma unroll
        for (int nt = 0; nt < 8; nt++)
            #pragma unroll
            for (int e = 0; e < 4; e++) sacc[nt][e] = 0.0f;
        #pragma unroll
        for (int kt = 0; kt < 4; kt++) {
            uint32_t af[4];
            const float* ap = sQ + r0 * QP + kt * 8 + tig;
            af[0] = __float_as_uint(ap[0]);
            af[1] = __float_as_uint(ap[8 * QP]);
            af[2] = __float_as_uint(ap[4]);
            af[3] = __float_as_uint(ap[8 * QP + 4]);
            #pragma unroll
            for (int nt = 0; nt < 8; nt++) {
                uint32_t bf[2];
                const float* bp = sK + (nt * 8 + gid) * QP + kt * 8 + tig;
                bf[0] = __float_as_uint(bp[0]);
                bf[1] = __float_as_uint(bp[4]);
                mma_tf32(sacc[nt], af, bf);
            }
        }

        // Softmax over rows r0, r1 (16 values each in regs + tig-quad shfl).
        float v0[16], v1[16];
        #pragma unroll
        for (int nt = 0; nt < 8; nt++) {
            #pragma unroll
            for (int e = 0; e < 2; e++) {
                int c = nt * 8 + tig * 2 + e;
                v0[nt * 2 + e] = sacc[nt][e] * SCALEF
                               + __ldg(&bt[(r0 - c + 63) * NHEAD + h])
                               + __ldg(&mrow[r0 * 64 + c]);
                v1[nt * 2 + e] = sacc[nt][2 + e] * SCALEF
                               + __ldg(&bt[(r1 - c + 63) * NHEAD + h])
                               + __ldg(&mrow[r1 * 64 + c]);
            }
        }
        float mx0 = -1e30f, mx1 = -1e30f;
        #pragma unroll
        for (int i = 0; i < 16; i++) { mx0 = fmaxf(mx0, v0[i]); mx1 = fmaxf(mx1, v1[i]); }
        mx0 = fmaxf(mx0, __shfl_xor_sync(0xffffffffu, mx0, 1));
        mx0 = fmaxf(mx0, __shfl_xor_sync(0xffffffffu, mx0, 2));
        mx1 = fmaxf(mx1, __shfl_xor_sync(0xffffffffu, mx1, 1));
        mx1 = fmaxf(mx1, __shfl_xor_sync(0xffffffffu, mx1, 2));
        float s0 = 0.0f, s1 = 0.0f;
        #pragma unroll
        for (int i = 0; i < 16; i++) {
            v0[i] = __expf(v0[i] - mx0); s0 += v0[i];
            v1[i] = __expf(v1[i] - mx1); s1 += v1[i];
        }
        s0 += __shfl_xor_sync(0xffffffffu, s0, 1);
        s0 += __shfl_xor_sync(0xffffffffu, s0, 2);
        s1 += __shfl_xor_sync(0xffffffffu, s1, 1);
        s1 += __shfl_xor_sync(0xffffffffu, s1, 2);
        const float i0 = 1.0f / s0, i1 = 1.0f / s1;
        #pragma unroll
        for (int nt = 0; nt < 8; nt++) {
            int c = nt * 8 + tig * 2;
            float2 p0 = make_float2(tf32r(v0[nt * 2] * i0), tf32r(v0[nt * 2 + 1] * i0));
            float2 p1 = make_float2(tf32r(v1[nt * 2] * i1), tf32r(v1[nt * 2 + 1] * i1));
            *(float2*)&sP[r0 * PP + c] = p0;
            *(float2*)&sP[r1 * PP + c] = p1;
        }
        __syncwarp();   // P rows are warp-private: warp-level visibility suffices

        // O = P @ V : warp rows r0/r1, 4 n-tiles over head dim 32, k=64.
        float oacc[4][4];
        #pragma unroll
        for (int nt = 0; nt < 4; nt++)
            #pragma unroll
            for (int e = 0; e < 4; e++) oacc[nt][e] = 0.0f;
        #pragma unroll
        for (int kt = 0; kt < 8; kt++) {
            uint32_t af[4];
            const float* pp = sP + r0 * PP + kt * 8 + tig;
            af[0] = __float_as_uint(pp[0]);
            af[1] = __float_as_uint(pp[8 * PP]);
            af[2] = __float_as_uint(pp[4]);
            af[3] = __float_as_uint(pp[8 * PP + 4]);
            #pragma unroll
            for (int nt = 0; nt < 4; nt++) {
                uint32_t bf[2];
                const float* vp = sVt + (nt * 8 + gid) * VP + kt * 8 + tig;
                bf[0] = __float_as_uint(vp[0]);
                bf[1] = __float_as_uint(vp[4]);
                mma_tf32(oacc[nt], af, bf);
            }
        }
        #pragma unroll
        for (int nt = 0; nt < 4; nt++) {
            const int c = h * 32 + nt * 8 + tig * 2;
            *(float2*)&og[r0 * 256 + c] = make_float2(oacc[nt][0], oacc[nt][1]);
            *(float2*)&og[r1 * 256 + c] = make_float2(oacc[nt][2], oacc[nt][3]);
        }
    }
}

// ---------------------------------------------------------------------------
extern "C" void kernel_launch(void* const* d_in, const int* in_sizes, int n_in,
                              void* d_out, int out_size)
{
    const float* x          = (const float*)d_in[0];
    const float* mask       = (const float*)d_in[1];
    const float* wqkv       = (const float*)d_in[2];
    const float* bqkv       = (const float*)d_in[3];
    const float* wproj      = (const float*)d_in[4];
    const float* bproj      = (const float*)d_in[5];
    const float* bias_table = (const float*)d_in[6];
    (void)in_sizes; (void)n_in; (void)out_size;

    cudaFuncSetAttribute(gemm_tf32, cudaFuncAttributeMaxDynamicSharedMemorySize, GEMM_SMEM);
    cudaFuncSetAttribute(wattn, cudaFuncAttributeMaxDynamicSharedMemorySize, WATTN_SMEM);

    float *qkvT, *projT, *qkvS, *oS;
    cudaGetSymbolAddress((void**)&qkvT,  g_WqkvT);
    cudaGetSymbolAddress((void**)&projT, g_WprojT);
    cudaGetSymbolAddress((void**)&qkvS,  g_QKV);
    cudaGetSymbolAddress((void**)&oS,    g_O);

    transpose_tf32<<<dim3(24, 8), dim3(32, 8)>>>(wqkv,  qkvT, 768);
    transpose_tf32<<<dim3(8, 8),  dim3(32, 8)>>>(wproj, projT, 256);
    gemm_tf32<<<2048, 256, GEMM_SMEM>>>(x, qkvT, bqkv, qkvS, 768);
    wattn<<<NWIN, 256, WATTN_SMEM>>>(qkvS, mask, bias_table, oS);
    gemm_tf32<<<2048, 256, GEMM_SMEM>>>(oS, projT, bproj, (float*)d_out, 256);
}

// round 8
// speedup vs baseline: 3.7511x; 1.0463x over previous
#include <cuda_runtime.h>
#include <cstdint>

// Window attention: B_=4096 windows, N=64 tok, C=256, H=8 heads, D=32. fp32 I/O.
//   t0: transpose+round w_qkv/w_proj -> g_W*T (tf32)
//   k1: A-resident N-looped mma.sync tf32 GEMM  g_QKV = x @ WqkvT^T + b_qkv
//   k2: mma.sync tf32 attention, mask/bias staged in smem -> g_O
//   k3: same GEMM  out = g_O @ WprojT^T + b_proj
// (PTX target compute_103: tcgen05 unavailable; legacy mma.sync tf32 path.)

#define NWIN   4096
#define CDIM   256
#define NHEAD  8
#define SCALEF 0.17677669529663687f

__device__ float g_QKV[(size_t)NWIN * 64 * 768];
__device__ float g_O  [(size_t)NWIN * 64 * 256];
__device__ float g_WqkvT [768 * 256];
__device__ float g_WprojT[256 * 256];

__device__ __forceinline__ float tf32r(float x) {
    float y; asm("cvt.rna.tf32.f32 %0, %1;" : "=f"(y) : "f"(x)); return y;
}
__device__ __forceinline__ uint32_t smem_u32(const void* p) {
    uint32_t a;
    asm("{ .reg .u64 t; cvta.to.shared.u64 t, %1; cvt.u32.u64 %0, t; }" : "=r"(a) : "l"(p));
    return a;
}
__device__ __forceinline__ void cp_async16(uint32_t dst, const void* src) {
    asm volatile("cp.async.cg.shared.global [%0], [%1], 16;" :: "r"(dst), "l"(src));
}
__device__ __forceinline__ void cp_commit() {
    asm volatile("cp.async.commit_group;" ::: "memory");
}
template<int N> __device__ __forceinline__ void cp_wait() {
    asm volatile("cp.async.wait_group %0;" :: "n"(N) : "memory");
}

// m16n8k8 tf32 mma: D += A(16x8,row) * B(8x8,col).
__device__ __forceinline__ void mma_tf32(float* d, const uint32_t* a, const uint32_t* b) {
    asm volatile(
        "mma.sync.aligned.m16n8k8.row.col.f32.tf32.tf32.f32 "
        "{%0,%1,%2,%3}, {%4,%5,%6,%7}, {%8,%9}, {%0,%1,%2,%3};"
        : "+f"(d[0]), "+f"(d[1]), "+f"(d[2]), "+f"(d[3])
        : "r"(a[0]), "r"(a[1]), "r"(a[2]), "r"(a[3]), "r"(b[0]), "r"(b[1]));
}

// ---------------------------------------------------------------------------
// Kernel t0: transpose src[256, ncol] -> dst[ncol, 256], tf32-rounded.
// ---------------------------------------------------------------------------
__global__ void transpose_tf32(const float* __restrict__ src, float* __restrict__ dst, int ncol)
{
    __shared__ float tile[32][33];
    const int bx = blockIdx.x, by = blockIdx.y;
    const int tx = threadIdx.x, ty0 = threadIdx.y;
    #pragma unroll
    for (int j = 0; j < 32; j += 8)
        tile[ty0 + j][tx] = src[(size_t)(by * 32 + ty0 + j) * ncol + bx * 32 + tx];
    __syncthreads();
    #pragma unroll
    for (int j = 0; j < 32; j += 8)
        dst[(size_t)(bx * 32 + ty0 + j) * 256 + by * 32 + tx] = tf32r(tile[tx][ty0 + j]);
}

// ---------------------------------------------------------------------------
// Kernel k1/k3: A-resident, N-looped mma.sync tf32 GEMM.
// C[Mtot, ncols] = A[Mtot,256] @ BT^T + bias.  3-stage cp.async B pipeline,
// ONE __syncthreads per K-chunk (loads for kc+2 issued after compute of kc).
// 256 thr = 8 warps (4m x 2n), warp tile 32x64.
// ---------------------------------------------------------------------------
#define BM 128
#define BK 32
#define APAD 260
#define BPAD 36
#define BSTAGE (BM * BPAD)                          // 4608 floats
#define NSTAGE 3
#define GEMM_SMEM ((BM * APAD + NSTAGE * BSTAGE) * 4)  // 188416 B

__global__ void __launch_bounds__(256, 1) gemm_tf32(
    const float* __restrict__ A, const float* __restrict__ BT,
    const float* __restrict__ bias, float* __restrict__ C, int ncols)
{
    extern __shared__ float sm[];
    float* sA = sm;                        // [128][APAD]
    float* sB = sm + BM * APAD;            // [3][128][BPAD]

    const int t = threadIdx.x;
    const int wid = t >> 5, lane = t & 31;
    const int wm = wid & 3, wn = wid >> 2;
    const int gid = lane >> 2, tig = lane & 3;
    const int m0 = blockIdx.x * BM;
    const uint32_t sBu = smem_u32(sB);

    // Stage A resident [128x256], tf32-rounded.
    #pragma unroll
    for (int i = 0; i < 32; i++) {
        int f = t + i * 256;               // float4 idx 0..8191
        int r = f >> 6, c4 = f & 63;
        float4 v = __ldg((const float4*)(A + (size_t)(m0 + r) * CDIM) + c4);
        v.x = tf32r(v.x); v.y = tf32r(v.y); v.z = tf32r(v.z); v.w = tf32r(v.w);
        *(float4*)(sA + r * APAD + c4 * 4) = v;
    }

    auto loadB = [&](int n0, int kc, int s) {
        #pragma unroll
        for (int i = 0; i < 4; i++) {
            int f = t + i * 256;           // 0..1023
            int r = f >> 3, c4 = f & 7;
            cp_async16(sBu + (uint32_t)(s * BSTAGE + r * BPAD + c4 * 4) * 4,
                       BT + (size_t)(n0 + r) * CDIM + kc * BK + c4 * 4);
        }
    };

    const int ntiles = ncols >> 7;
    for (int nt = 0; nt < ntiles; nt++) {
        const int n0 = nt << 7;

        float acc[2][8][4];
        #pragma unroll
        for (int mt = 0; mt < 2; mt++)
            #pragma unroll
            for (int ntt = 0; ntt < 8; ntt++)
                #pragma unroll
                for (int e = 0; e < 4; e++) acc[mt][ntt][e] = 0.0f;

        loadB(n0, 0, 0); cp_commit();
        loadB(n0, 1, 1); cp_commit();

        #pragma unroll 1
        for (int kc = 0; kc < CDIM / BK; kc++) {
            if (kc < CDIM / BK - 1) cp_wait<1>(); else cp_wait<0>();
            __syncthreads();   // chunk kc visible everywhere; all done with kc-1

            const float* b_s = sB + (kc % NSTAGE) * BSTAGE;
            #pragma unroll
            for (int kk = 0; kk < BK; kk += 8) {
                uint32_t af[2][4], bf[8][2];
                #pragma unroll
                for (int mt = 0; mt < 2; mt++) {
                    const float* ap = sA + (wm * 32 + mt * 16 + gid) * APAD + kc * BK + kk + tig;
                    af[mt][0] = __float_as_uint(ap[0]);
                    af[mt][1] = __float_as_uint(ap[8 * APAD]);
                    af[mt][2] = __float_as_uint(ap[4]);
                    af[mt][3] = __float_as_uint(ap[8 * APAD + 4]);
                }
                #pragma unroll
                for (int ntt = 0; ntt < 8; ntt++) {
                    const float* bp = b_s + (wn * 64 + ntt * 8 + gid) * BPAD + kk + tig;
                    bf[ntt][0] = __float_as_uint(bp[0]);
                    bf[ntt][1] = __float_as_uint(bp[4]);
                }
                #pragma unroll
                for (int mt = 0; mt < 2; mt++)
                    #pragma unroll
                    for (int ntt = 0; ntt < 8; ntt++)
                        mma_tf32(acc[mt][ntt], af[mt], bf[ntt]);
            }
            // Prefetch chunk kc+2 into the stage freed by chunk kc-1.
            if (kc + 2 < CDIM / BK) { loadB(n0, kc + 2, (kc + 2) % NSTAGE); cp_commit(); }
        }

        // Epilogue for this n-tile (regs -> gmem, no smem).
        #pragma unroll
        for (int mt = 0; mt < 2; mt++) {
            const int r = m0 + wm * 32 + mt * 16 + gid;
            #pragma unroll
            for (int ntt = 0; ntt < 8; ntt++) {
                const int c = n0 + wn * 64 + ntt * 8 + tig * 2;
                float b0 = __ldg(bias + c), b1 = __ldg(bias + c + 1);
                float2 v0 = make_float2(acc[mt][ntt][0] + b0, acc[mt][ntt][1] + b1);
                float2 v1 = make_float2(acc[mt][ntt][2] + b0, acc[mt][ntt][3] + b1);
                *(float2*)(C + (size_t)r * ncols + c)       = v0;
                *(float2*)(C + (size_t)(r + 8) * ncols + c) = v1;
            }
        }
        __syncthreads();   // all reads of chunks 6,7 done before next tile's preload
    }
}

// ---------------------------------------------------------------------------
// Kernel k2: tensor-core attention.
// 8 warps = 2 warp-groups; wg handles head (hp*2+wg), hp=0..3.
// Mask staged ONCE per CTA in smem [64][68]; per-head bias column staged per
// wg [127] -> softmax does LDS instead of scattered gmem gathers.
// ---------------------------------------------------------------------------
#define QP 36
#define VP 68
#define PP 68
// float offsets
#define OFF_Q(wg)   ((wg) * 2304)
#define OFF_K(wg)   (4608 + (wg) * 2304)
#define OFF_VT(wg)  (9216 + (wg) * 2176)
#define OFF_P(wg)   (13568 + (wg) * 4352)
#define OFF_MASK    22272
#define OFF_BIAS(wg) (26624 + (wg) * 128)
#define WATTN_SMEM  (26880 * 4)   // 107520 B -> 2 CTAs/SM

__global__ void __launch_bounds__(256) wattn(
    const float* __restrict__ qkv, const float* __restrict__ mask,
    const float* __restrict__ bt, float* __restrict__ O)
{
    extern __shared__ float sm[];
    const int t = threadIdx.x, wid = t >> 5, lane = t & 31;
    const int wg = wid >> 2, wm = wid & 3;
    const int gid = lane >> 2, tig = lane & 3;
    const int tt = t & 127;
    const int b = blockIdx.x;

    float* sQ    = sm + OFF_Q(wg);
    float* sK    = sm + OFF_K(wg);
    float* sVt   = sm + OFF_VT(wg);
    float* sP    = sm + OFF_P(wg);
    float* sMask = sm + OFF_MASK;
    float* sBias = sm + OFF_BIAS(wg);

    const float* base = qkv + (size_t)b * (64 * 768);
    const float* mrow = mask + (size_t)(b & 63) * 4096;
    float* og = O + (size_t)b * (64 * 256);

    // Stage mask [64][68] once (float4), reused by all heads.
    #pragma unroll
    for (int i = 0; i < 4; i++) {
        int f4 = t + i * 256;              // 0..1023
        int r = f4 >> 4, c4 = f4 & 15;
        *(float4*)&sMask[r * 68 + c4 * 4] = ((const float4*)mrow)[f4];
    }

    const int r0 = wm * 16 + gid, r1 = r0 + 8;

    for (int hp = 0; hp < 4; hp++) {
        const int h = hp * 2 + wg;
        __syncthreads();   // previous iteration's smem reads done (covers mask on hp=0)
        // Stage this wg's head: Q,K row-major [64][QP]; V transposed [32][VP].
        #pragma unroll
        for (int i = 0; i < 4; i++) {
            int u = tt + i * 128;          // 0..511
            int n = u >> 3, q = u & 7;
            const float4* rp = (const float4*)(base + n * 768 + h * 32) + q;
            float4 qa = rp[0];
            qa.x = tf32r(qa.x); qa.y = tf32r(qa.y); qa.z = tf32r(qa.z); qa.w = tf32r(qa.w);
            *(float4*)&sQ[n * QP + q * 4] = qa;
            float4 ka = rp[64];            // +256 floats
            ka.x = tf32r(ka.x); ka.y = tf32r(ka.y); ka.z = tf32r(ka.z); ka.w = tf32r(ka.w);
            *(float4*)&sK[n * QP + q * 4] = ka;
            float4 va = rp[128];           // +512 floats
            sVt[(q * 4 + 0) * VP + n] = tf32r(va.x);
            sVt[(q * 4 + 1) * VP + n] = tf32r(va.y);
            sVt[(q * 4 + 2) * VP + n] = tf32r(va.z);
            sVt[(q * 4 + 3) * VP + n] = tf32r(va.w);
        }
        // Stage bias column for this head: idx 0..126 -> bt[idx*8+h].
        if (tt < 127) sBias[tt] = __ldg(&bt[tt * 8 + h]);
        __syncthreads();

        // S = Q K^T : warp covers rows wm*16..+15, all 64 cols (8 n-tiles).
        float sacc[8][4];
        #pragma unroll
        for (int nt = 0; nt < 8; nt++)
            #pragma unroll
            for (int e = 0; e < 4; e++) sacc[nt][e] = 0.0f;
        #pragma unroll
        for (int kt = 0; kt < 4; kt++) {
            uint32_t af[4];
            const float* ap = sQ + r0 * QP + kt * 8 + tig;
            af[0] = __float_as_uint(ap[0]);
            af[1] = __float_as_uint(ap[8 * QP]);
            af[2] = __float_as_uint(ap[4]);
            af[3] = __float_as_uint(ap[8 * QP + 4]);
            #pragma unroll
            for (int nt = 0; nt < 8; nt++) {
                uint32_t bf[2];
                const float* bp = sK + (nt * 8 + gid) * QP + kt * 8 + tig;
                bf[0] = __float_as_uint(bp[0]);
                bf[1] = __float_as_uint(bp[4]);
                mma_tf32(sacc[nt], af, bf);
            }
        }

        // Softmax over rows r0, r1; bias+mask from smem.
        float v0[16], v1[16];
        #pragma unroll
        for (int nt = 0; nt < 8; nt++) {
            #pragma unroll
            for (int e = 0; e < 2; e++) {
                int c = nt * 8 + tig * 2 + e;
                v0[nt * 2 + e] = fmaf(sacc[nt][e],     SCALEF,
                                      sBias[r0 - c + 63] + sMask[r0 * 68 + c]);
                v1[nt * 2 + e] = fmaf(sacc[nt][2 + e], SCALEF,
                                      sBias[r1 - c + 63] + sMask[r1 * 68 + c]);
            }
        }
        float mx0 = -1e30f, mx1 = -1e30f;
        #pragma unroll
        for (int i = 0; i < 16; i++) { mx0 = fmaxf(mx0, v0[i]); mx1 = fmaxf(mx1, v1[i]); }
        mx0 = fmaxf(mx0, __shfl_xor_sync(0xffffffffu, mx0, 1));
        mx0 = fmaxf(mx0, __shfl_xor_sync(0xffffffffu, mx0, 2));
        mx1 = fmaxf(mx1, __shfl_xor_sync(0xffffffffu, mx1, 1));
        mx1 = fmaxf(mx1, __shfl_xor_sync(0xffffffffu, mx1, 2));
        float s0 = 0.0f, s1 = 0.0f;
        #pragma unroll
        for (int i = 0; i < 16; i++) {
            v0[i] = __expf(v0[i] - mx0); s0 += v0[i];
            v1[i] = __expf(v1[i] - mx1); s1 += v1[i];
        }
        s0 += __shfl_xor_sync(0xffffffffu, s0, 1);
        s0 += __shfl_xor_sync(0xffffffffu, s0, 2);
        s1 += __shfl_xor_sync(0xffffffffu, s1, 1);
        s1 += __shfl_xor_sync(0xffffffffu, s1, 2);
        const float i0 = 1.0f / s0, i1 = 1.0f / s1;
        #pragma unroll
        for (int nt = 0; nt < 8; nt++) {
            int c = nt * 8 + tig * 2;
            float2 p0 = make_float2(tf32r(v0[nt * 2] * i0), tf32r(v0[nt * 2 + 1] * i0));
            float2 p1 = make_float2(tf32r(v1[nt * 2] * i1), tf32r(v1[nt * 2 + 1] * i1));
            *(float2*)&sP[r0 * PP + c] = p0;
            *(float2*)&sP[r1 * PP + c] = p1;
        }
        __syncwarp();   // P rows are warp-private

        // O = P @ V : warp rows r0/r1, 4 n-tiles over head dim 32, k=64.
        float oacc[4][4];
        #pragma unroll
        for (int nt = 0; nt < 4; nt++)
            #pragma unroll
            for (int e = 0; e < 4; e++) oacc[nt][e] = 0.0f;
        #pragma unroll
        for (int kt = 0; kt < 8; kt++) {
            uint32_t af[4];
            const float* pp = sP + r0 * PP + kt * 8 + tig;
            af[0] = __float_as_uint(pp[0]);
            af[1] = __float_as_uint(pp[8 * PP]);
            af[2] = __float_as_uint(pp[4]);
            af[3] = __float_as_uint(pp[8 * PP + 4]);
            #pragma unroll
            for (int nt = 0; nt < 4; nt++) {
                uint32_t bf[2];
                const float* vp = sVt + (nt * 8 + gid) * VP + kt * 8 + tig;
                bf[0] = __float_as_uint(vp[0]);
                bf[1] = __float_as_uint(vp[4]);
                mma_tf32(oacc[nt], af, bf);
            }
        }
        #pragma unroll
        for (int nt = 0; nt < 4; nt++) {
            const int c = h * 32 + nt * 8 + tig * 2;
            *(float2*)&og[r0 * 256 + c] = make_float2(oacc[nt][0], oacc[nt][1]);
            *(float2*)&og[r1 * 256 + c] = make_float2(oacc[nt][2], oacc[nt][3]);
        }
    }
}

// ---------------------------------------------------------------------------
extern "C" void kernel_launch(void* const* d_in, const int* in_sizes, int n_in,
                              void* d_out, int out_size)
{
    const float* x          = (const float*)d_in[0];
    const float* mask       = (const float*)d_in[1];
    const float* wqkv       = (const float*)d_in[2];
    const float* bqkv       = (const float*)d_in[3];
    const float* wproj      = (const float*)d_in[4];
    const float* bproj      = (const float*)d_in[5];
    const float* bias_table = (const float*)d_in[6];
    (void)in_sizes; (void)n_in; (void)out_size;

    cudaFuncSetAttribute(gemm_tf32, cudaFuncAttributeMaxDynamicSharedMemorySize, GEMM_SMEM);
    cudaFuncSetAttribute(wattn, cudaFuncAttributeMaxDynamicSharedMemorySize, WATTN_SMEM);

    float *qkvT, *projT, *qkvS, *oS;
    cudaGetSymbolAddress((void**)&qkvT,  g_WqkvT);
    cudaGetSymbolAddress((void**)&projT, g_WprojT);
    cudaGetSymbolAddress((void**)&qkvS,  g_QKV);
    cudaGetSymbolAddress((void**)&oS,    g_O);

    transpose_tf32<<<dim3(24, 8), dim3(32, 8)>>>(wqkv,  qkvT, 768);
    transpose_tf32<<<dim3(8, 8),  dim3(32, 8)>>>(wproj, projT, 256);
    gemm_tf32<<<2048, 256, GEMM_SMEM>>>(x, qkvT, bqkv, qkvS, 768);
    wattn<<<NWIN, 256, WATTN_SMEM>>>(qkvS, mask, bias_table, oS);
    gemm_tf32<<<2048, 256, GEMM_SMEM>>>(oS, projT, bproj, (float*)d_out, 256);
}

// round 9
// speedup vs baseline: 4.2259x; 1.1266x over previous
#include <cuda_runtime.h>
#include <cstdint>

// Window attention: B_=4096 windows, N=64 tok, C=256, H=8 heads, D=32. fp32 I/O.
//   r0: g_Xr = tf32-round(x)
//   t0: transpose+round w_qkv/w_proj -> g_W*T (tf32)
//   k1: 3-stage cp.async mma.sync tf32 GEMM, grid (n,m) for L2 reuse of A
//   k2: mma.sync tf32 attention, wg-named barriers, Q/K reg prefetch -> g_O (rounded)
//   k3: same GEMM for proj
// (PTX target compute_103: tcgen05 unavailable; legacy mma.sync tf32 path.)

#define NWIN   4096
#define CDIM   256
#define NHEAD  8
#define SCALEF 0.17677669529663687f

__device__ float g_QKV[(size_t)NWIN * 64 * 768];
__device__ float g_O  [(size_t)NWIN * 64 * 256];
__device__ float g_Xr [(size_t)NWIN * 64 * 256];
__device__ float g_WqkvT [768 * 256];
__device__ float g_WprojT[256 * 256];

__device__ __forceinline__ float tf32r(float x) {
    float y; asm("cvt.rna.tf32.f32 %0, %1;" : "=f"(y) : "f"(x)); return y;
}
__device__ __forceinline__ uint32_t smem_u32(const void* p) {
    uint32_t a;
    asm("{ .reg .u64 t; cvta.to.shared.u64 t, %1; cvt.u32.u64 %0, t; }" : "=r"(a) : "l"(p));
    return a;
}
__device__ __forceinline__ void cp_async16(uint32_t dst, const void* src) {
    asm volatile("cp.async.cg.shared.global [%0], [%1], 16;" :: "r"(dst), "l"(src));
}
__device__ __forceinline__ void cp_commit() {
    asm volatile("cp.async.commit_group;" ::: "memory");
}
template<int N> __device__ __forceinline__ void cp_wait() {
    asm volatile("cp.async.wait_group %0;" :: "n"(N) : "memory");
}

// m16n8k8 tf32 mma: D += A(16x8,row) * B(8x8,col).
__device__ __forceinline__ void mma_tf32(float* d, const uint32_t* a, const uint32_t* b) {
    asm volatile(
        "mma.sync.aligned.m16n8k8.row.col.f32.tf32.tf32.f32 "
        "{%0,%1,%2,%3}, {%4,%5,%6,%7}, {%8,%9}, {%0,%1,%2,%3};"
        : "+f"(d[0]), "+f"(d[1]), "+f"(d[2]), "+f"(d[3])
        : "r"(a[0]), "r"(a[1]), "r"(a[2]), "r"(a[3]), "r"(b[0]), "r"(b[1]));
}

// ---------------------------------------------------------------------------
// Kernel r0: elementwise tf32 rounding (float4).
// ---------------------------------------------------------------------------
__global__ void round_tf32(const float4* __restrict__ in, float4* __restrict__ out)
{
    int i = blockIdx.x * blockDim.x + threadIdx.x;
    float4 v = in[i];
    v.x = tf32r(v.x); v.y = tf32r(v.y); v.z = tf32r(v.z); v.w = tf32r(v.w);
    out[i] = v;
}

// ---------------------------------------------------------------------------
// Kernel t0: transpose src[256, ncol] -> dst[ncol, 256], tf32-rounded.
// ---------------------------------------------------------------------------
__global__ void transpose_tf32(const float* __restrict__ src, float* __restrict__ dst, int ncol)
{
    __shared__ float tile[32][33];
    const int bx = blockIdx.x, by = blockIdx.y;
    const int tx = threadIdx.x, ty0 = threadIdx.y;
    #pragma unroll
    for (int j = 0; j < 32; j += 8)
        tile[ty0 + j][tx] = src[(size_t)(by * 32 + ty0 + j) * ncol + bx * 32 + tx];
    __syncthreads();
    #pragma unroll
    for (int j = 0; j < 32; j += 8)
        dst[(size_t)(bx * 32 + ty0 + j) * 256 + by * 32 + tx] = tf32r(tile[tx][ty0 + j]);
}

// ---------------------------------------------------------------------------
// Kernel k1/k3: 3-stage cp.async mma.sync tf32 GEMM.
// C[Mtot, ncols] = A[Mtot,256] @ BT^T + bias.  A,BT pre-rounded tf32.
// CTA tile 128x128; grid.x = n-tile (adjacent CTAs share A m-tile -> L2),
// grid.y = m-tile.  One __syncthreads per K-chunk; loads kc+2 after compute.
// 256 thr = 8 warps (4m x 2n), warp tile 32x64.  2 CTAs/SM.
// ---------------------------------------------------------------------------
#define BM 128
#define BK 32
#define KP 36
#define STG (BM * KP)                       // 4608 floats
#define NST 3
#define GEMM_SMEM (2 * NST * STG * 4)       // 110592 B

__global__ void __launch_bounds__(256, 2) gemm_tf32(
    const float* __restrict__ A, const float* __restrict__ BT,
    const float* __restrict__ bias, float* __restrict__ C, int ncols)
{
    extern __shared__ float sm[];
    float* sA = sm;                         // [3][128][KP]
    float* sB = sm + NST * STG;             // [3][128][KP]

    const int t = threadIdx.x;
    const int wid = t >> 5, lane = t & 31;
    const int wm = wid & 3, wn = wid >> 2;
    const int gid = lane >> 2, tig = lane & 3;
    const int n0 = blockIdx.x * BM;
    const int m0 = blockIdx.y * BM;
    const uint32_t sAu = smem_u32(sA);
    const uint32_t sBu = smem_u32(sB);

    auto loadAB = [&](int kc, int s) {
        #pragma unroll
        for (int i = 0; i < 4; i++) {
            int f = t + i * 256;            // 0..1023
            int r = f >> 3, c4 = f & 7;
            cp_async16(sAu + (uint32_t)(s * STG + r * KP + c4 * 4) * 4,
                       A + (size_t)(m0 + r) * CDIM + kc * BK + c4 * 4);
        }
        #pragma unroll
        for (int i = 0; i < 4; i++) {
            int f = t + i * 256;
            int r = f >> 3, c4 = f & 7;
            cp_async16(sBu + (uint32_t)(s * STG + r * KP + c4 * 4) * 4,
                       BT + (size_t)(n0 + r) * CDIM + kc * BK + c4 * 4);
        }
    };

    float acc[2][8][4];
    #pragma unroll
    for (int mt = 0; mt < 2; mt++)
        #pragma unroll
        for (int nt = 0; nt < 8; nt++)
            #pragma unroll
            for (int e = 0; e < 4; e++) acc[mt][nt][e] = 0.0f;

    loadAB(0, 0); cp_commit();
    loadAB(1, 1); cp_commit();

    #pragma unroll 1
    for (int kc = 0; kc < CDIM / BK; kc++) {
        if (kc < CDIM / BK - 1) cp_wait<1>(); else cp_wait<0>();
        __syncthreads();   // chunk kc visible; all warps done with chunk kc-1

        const float* a_s = sA + (kc % NST) * STG;
        const float* b_s = sB + (kc % NST) * STG;
        #pragma unroll
        for (int kk = 0; kk < BK; kk += 8) {
            uint32_t af[2][4], bf[8][2];
            #pragma unroll
            for (int mt = 0; mt < 2; mt++) {
                const float* ap = a_s + (wm * 32 + mt * 16 + gid) * KP + kk + tig;
                af[mt][0] = __float_as_uint(ap[0]);
                af[mt][1] = __float_as_uint(ap[8 * KP]);
                af[mt][2] = __float_as_uint(ap[4]);
                af[mt][3] = __float_as_uint(ap[8 * KP + 4]);
            }
            #pragma unroll
            for (int nt = 0; nt < 8; nt++) {
                const float* bp = b_s + (wn * 64 + nt * 8 + gid) * KP + kk + tig;
                bf[nt][0] = __float_as_uint(bp[0]);
                bf[nt][1] = __float_as_uint(bp[4]);
            }
            #pragma unroll
            for (int mt = 0; mt < 2; mt++)
                #pragma unroll
                for (int nt = 0; nt < 8; nt++)
                    mma_tf32(acc[mt][nt], af[mt], bf[nt]);
        }
        if (kc + 2 < CDIM / BK) { loadAB(kc + 2, (kc + 2) % NST); cp_commit(); }
    }

    // Epilogue: bias + store (regs -> gmem).
    #pragma unroll
    for (int mt = 0; mt < 2; mt++) {
        const int r = m0 + wm * 32 + mt * 16 + gid;
        #pragma unroll
        for (int nt = 0; nt < 8; nt++) {
            const int c = n0 + wn * 64 + nt * 8 + tig * 2;
            float b0 = __ldg(bias + c), b1 = __ldg(bias + c + 1);
            float2 v0 = make_float2(acc[mt][nt][0] + b0, acc[mt][nt][1] + b1);
            float2 v1 = make_float2(acc[mt][nt][2] + b0, acc[mt][nt][3] + b1);
            *(float2*)(C + (size_t)r * ncols + c)       = v0;
            *(float2*)(C + (size_t)(r + 8) * ncols + c) = v1;
        }
    }
}

// ---------------------------------------------------------------------------
// Kernel k2: tensor-core attention.
// 2 warp-groups; wg handles head (hp*2+wg), hp=0..3.  Per-wg NAMED barriers
// (bar.sync 1+wg) so wgs run independently; Q/K of next head prefetched into
// registers during current head's compute.  Mask/bias staged in smem.
// Writes g_O tf32-rounded (feeds proj GEMM's cp.async path).
// ---------------------------------------------------------------------------
#define QP 36
#define VP 68
#define PP 68
#define OFF_Q(wg)   ((wg) * 2304)
#define OFF_K(wg)   (4608 + (wg) * 2304)
#define OFF_VT(wg)  (9216 + (wg) * 2176)
#define OFF_P(wg)   (13568 + (wg) * 4352)
#define OFF_MASK    22272
#define OFF_BIAS(wg) (26624 + (wg) * 128)
#define WATTN_SMEM  (26880 * 4)   // 107520 B -> 2 CTAs/SM

__global__ void __launch_bounds__(256, 2) wattn(
    const float* __restrict__ qkv, const float* __restrict__ mask,
    const float* __restrict__ bt, float* __restrict__ O)
{
    extern __shared__ float sm[];
    const int t = threadIdx.x, wid = t >> 5, lane = t & 31;
    const int wg = wid >> 2, wm = wid & 3;
    const int gid = lane >> 2, tig = lane & 3;
    const int tt = t & 127;
    const int b = blockIdx.x;
    const int barid = 1 + wg;

    float* sQ    = sm + OFF_Q(wg);
    float* sK    = sm + OFF_K(wg);
    float* sVt   = sm + OFF_VT(wg);
    float* sP    = sm + OFF_P(wg);
    float* sMask = sm + OFF_MASK;
    float* sBias = sm + OFF_BIAS(wg);

    const float* base = qkv + (size_t)b * (64 * 768);
    const float* mrow = mask + (size_t)(b & 63) * 4096;
    float* og = O + (size_t)b * (64 * 256);

    // Stage mask [64][68] once (float4), reused by all heads / both wgs.
    #pragma unroll
    for (int i = 0; i < 4; i++) {
        int f4 = t + i * 256;
        int r = f4 >> 4, c4 = f4 & 15;
        *(float4*)&sMask[r * 68 + c4 * 4] = ((const float4*)mrow)[f4];
    }

    // Prefetch head hp=0 Q/K into registers.
    float4 pq[4], pk[4];
    #pragma unroll
    for (int i = 0; i < 4; i++) {
        int u = tt + i * 128;
        int n = u >> 3, q = u & 7;
        const float4* rp = (const float4*)(base + n * 768 + wg * 32) + q;
        pq[i] = rp[0];
        pk[i] = rp[64];
    }

    __syncthreads();   // mask visible to both wgs

    const int r0 = wm * 16 + gid, r1 = r0 + 8;

    for (int hp = 0; hp < 4; hp++) {
        const int h = hp * 2 + wg;
        asm volatile("bar.sync %0, 128;" :: "r"(barid) : "memory");  // prev head reads done

        // Stage Q,K from prefetched regs; V via LDG+transpose.
        #pragma unroll
        for (int i = 0; i < 4; i++) {
            int u = tt + i * 128;
            int n = u >> 3, q = u & 7;
            float4 qa = pq[i];
            qa.x = tf32r(qa.x); qa.y = tf32r(qa.y); qa.z = tf32r(qa.z); qa.w = tf32r(qa.w);
            *(float4*)&sQ[n * QP + q * 4] = qa;
            float4 ka = pk[i];
            ka.x = tf32r(ka.x); ka.y = tf32r(ka.y); ka.z = tf32r(ka.z); ka.w = tf32r(ka.w);
            *(float4*)&sK[n * QP + q * 4] = ka;
            float4 va = *((const float4*)(base + n * 768 + h * 32) + q + 128);
            sVt[(q * 4 + 0) * VP + n] = tf32r(va.x);
            sVt[(q * 4 + 1) * VP + n] = tf32r(va.y);
            sVt[(q * 4 + 2) * VP + n] = tf32r(va.z);
            sVt[(q * 4 + 3) * VP + n] = tf32r(va.w);
        }
        if (tt < 127) sBias[tt] = __ldg(&bt[tt * 8 + h]);
        asm volatile("bar.sync %0, 128;" :: "r"(barid) : "memory");  // staging visible

        // Prefetch next head's Q/K (overlaps with compute below).
        if (hp < 3) {
            #pragma unroll
            for (int i = 0; i < 4; i++) {
                int u = tt + i * 128;
                int n = u >> 3, q = u & 7;
                const float4* rp = (const float4*)(base + n * 768 + (h + 2) * 32) + q;
                pq[i] = rp[0];
                pk[i] = rp[64];
            }
        }

        // S = Q K^T : warp rows wm*16..+15, 64 cols (8 n-tiles).
        float sacc[8][4];
        #pragma unroll
        for (int nt = 0; nt < 8; nt++)
            #pragma unroll
            for (int e = 0; e < 4; e++) sacc[nt][e] = 0.0f;
        #pragma unroll
        for (int kt = 0; kt < 4; kt++) {
            uint32_t af[4];
            const float* ap = sQ + r0 * QP + kt * 8 + tig;
            af[0] = __float_as_uint(ap[0]);
            af[1] = __float_as_uint(ap[8 * QP]);
            af[2] = __float_as_uint(ap[4]);
            af[3] = __float_as_uint(ap[8 * QP + 4]);
            #pragma unroll
            for (int nt = 0; nt < 8; nt++) {
                uint32_t bf[2];
                const float* bp = sK + (nt * 8 + gid) * QP + kt * 8 + tig;
                bf[0] = __float_as_uint(bp[0]);
                bf[1] = __float_as_uint(bp[4]);
                mma_tf32(sacc[nt], af, bf);
            }
        }

        // Softmax rows r0,r1; bias+mask from smem.
        float v0[16], v1[16];
        #pragma unroll
        for (int nt = 0; nt < 8; nt++) {
            #pragma unroll
            for (int e = 0; e < 2; e++) {
                int c = nt * 8 + tig * 2 + e;
                v0[nt * 2 + e] = fmaf(sacc[nt][e],     SCALEF,
                                      sBias[r0 - c + 63] + sMask[r0 * 68 + c]);
                v1[nt * 2 + e] = fmaf(sacc[nt][2 + e], SCALEF,
                                      sBias[r1 - c + 63] + sMask[r1 * 68 + c]);
            }
        }
        float mx0 = -1e30f, mx1 = -1e30f;
        #pragma unroll
        for (int i = 0; i < 16; i++) { mx0 = fmaxf(mx0, v0[i]); mx1 = fmaxf(mx1, v1[i]); }
        mx0 = fmaxf(mx0, __shfl_xor_sync(0xffffffffu, mx0, 1));
        mx0 = fmaxf(mx0, __shfl_xor_sync(0xffffffffu, mx0, 2));
        mx1 = fmaxf(mx1, __shfl_xor_sync(0xffffffffu, mx1, 1));
        mx1 = fmaxf(mx1, __shfl_xor_sync(0xffffffffu, mx1, 2));
        float s0 = 0.0f, s1 = 0.0f;
        #pragma unroll
        for (int i = 0; i < 16; i++) {
            v0[i] = __expf(v0[i] - mx0); s0 += v0[i];
            v1[i] = __expf(v1[i] - mx1); s1 += v1[i];
        }
        s0 += __shfl_xor_sync(0xffffffffu, s0, 1);
        s0 += __shfl_xor_sync(0xffffffffu, s0, 2);
        s1 += __shfl_xor_sync(0xffffffffu, s1, 1);
        s1 += __shfl_xor_sync(0xffffffffu, s1, 2);
        const float i0 = 1.0f / s0, i1 = 1.0f / s1;
        #pragma unroll
        for (int nt = 0; nt < 8; nt++) {
            int c = nt * 8 + tig * 2;
            float2 p0 = make_float2(tf32r(v0[nt * 2] * i0), tf32r(v0[nt * 2 + 1] * i0));
            float2 p1 = make_float2(tf32r(v1[nt * 2] * i1), tf32r(v1[nt * 2 + 1] * i1));
            *(float2*)&sP[r0 * PP + c] = p0;
            *(float2*)&sP[r1 * PP + c] = p1;
        }
        __syncwarp();   // P rows are warp-private

        // O = P @ V : 4 n-tiles over head dim 32, k=64.
        float oacc[4][4];
        #pragma unroll
        for (int nt = 0; nt < 4; nt++)
            #pragma unroll
            for (int e = 0; e < 4; e++) oacc[nt][e] = 0.0f;
        #pragma unroll
        for (int kt = 0; kt < 8; kt++) {
            uint32_t af[4];
            const float* pp = sP + r0 * PP + kt * 8 + tig;
            af[0] = __float_as_uint(pp[0]);
            af[1] = __float_as_uint(pp[8 * PP]);
            af[2] = __float_as_uint(pp[4]);
            af[3] = __float_as_uint(pp[8 * PP + 4]);
            #pragma unroll
            for (int nt = 0; nt < 4; nt++) {
                uint32_t bf[2];
                const float* vp = sVt + (nt * 8 + gid) * VP + kt * 8 + tig;
                bf[0] = __float_as_uint(vp[0]);
                bf[1] = __float_as_uint(vp[4]);
                mma_tf32(oacc[nt], af, bf);
            }
        }
        #pragma unroll
        for (int nt = 0; nt < 4; nt++) {
            const int c = h * 32 + nt * 8 + tig * 2;
            *(float2*)&og[r0 * 256 + c] =
                make_float2(tf32r(oacc[nt][0]), tf32r(oacc[nt][1]));
            *(float2*)&og[r1 * 256 + c] =
                make_float2(tf32r(oacc[nt][2]), tf32r(oacc[nt][3]));
        }
    }
}

// ---------------------------------------------------------------------------
extern "C" void kernel_launch(void* const* d_in, const int* in_sizes, int n_in,
                              void* d_out, int out_size)
{
    const float* x          = (const float*)d_in[0];
    const float* mask       = (const float*)d_in[1];
    const float* wqkv       = (const float*)d_in[2];
    const float* bqkv       = (const float*)d_in[3];
    const float* wproj      = (const float*)d_in[4];
    const float* bproj      = (const float*)d_in[5];
    const float* bias_table = (const float*)d_in[6];
    (void)in_sizes; (void)n_in; (void)out_size;

    cudaFuncSetAttribute(gemm_tf32, cudaFuncAttributeMaxDynamicSharedMemorySize, GEMM_SMEM);
    cudaFuncSetAttribute(wattn, cudaFuncAttributeMaxDynamicSharedMemorySize, WATTN_SMEM);

    float *qkvT, *projT, *qkvS, *oS, *xr;
    cudaGetSymbolAddress((void**)&qkvT,  g_WqkvT);
    cudaGetSymbolAddress((void**)&projT, g_WprojT);
    cudaGetSymbolAddress((void**)&qkvS,  g_QKV);
    cudaGetSymbolAddress((void**)&oS,    g_O);
    cudaGetSymbolAddress((void**)&xr,    g_Xr);

    round_tf32<<<65536, 256>>>((const float4*)x, (float4*)xr);
    transpose_tf32<<<dim3(24, 8), dim3(32, 8)>>>(wqkv,  qkvT, 768);
    transpose_tf32<<<dim3(8, 8),  dim3(32, 8)>>>(wproj, projT, 256);
    gemm_tf32<<<dim3(6, 2048), 256, GEMM_SMEM>>>(xr, qkvT, bqkv, qkvS, 768);
    wattn<<<NWIN, 256, WATTN_SMEM>>>(qkvS, mask, bias_table, oS);
    gemm_tf32<<<dim3(2, 2048), 256, GEMM_SMEM>>>(oS, projT, bproj, (float*)d_out, 256);
}

// round 10
// speedup vs baseline: 4.3287x; 1.0243x over previous
#include <cuda_runtime.h>
#include <cstdint>

// Window attention: B_=4096 windows, N=64 tok, C=256, H=8 heads, D=32. fp32 I/O.
//   r0: g_Xr = tf32-round(x)
//   t0: transpose+round w_qkv/w_proj -> g_W*T (tf32)
//   b0: g_BM[h][w] = bias+mask in MMA-fragment order (float4 per thread-tile)
//   k1: 3-stage cp.async mma.sync tf32 GEMM, grid (n,m) for L2 reuse of A
//   k2: mma.sync tf32 attention; bias+mask via coalesced LDG.128 from g_BM
//   k3: same GEMM for proj
// (PTX target compute_103: tcgen05 unavailable; legacy mma.sync tf32 path.)

#define NWIN   4096
#define CDIM   256
#define NHEAD  8
#define SCALEF 0.17677669529663687f

__device__ float  g_QKV[(size_t)NWIN * 64 * 768];
__device__ float  g_O  [(size_t)NWIN * 64 * 256];
__device__ float  g_Xr [(size_t)NWIN * 64 * 256];
__device__ float  g_WqkvT [768 * 256];
__device__ float  g_WprojT[256 * 256];
__device__ float4 g_BM[8 * 64 * 1024];      // 8 MB: [h][w][wm][nt][gid][tig]

__device__ __forceinline__ float tf32r(float x) {
    float y; asm("cvt.rna.tf32.f32 %0, %1;" : "=f"(y) : "f"(x)); return y;
}
__device__ __forceinline__ uint32_t smem_u32(const void* p) {
    uint32_t a;
    asm("{ .reg .u64 t; cvta.to.shared.u64 t, %1; cvt.u32.u64 %0, t; }" : "=r"(a) : "l"(p));
    return a;
}
__device__ __forceinline__ void cp_async16(uint32_t dst, const void* src) {
    asm volatile("cp.async.cg.shared.global [%0], [%1], 16;" :: "r"(dst), "l"(src));
}
__device__ __forceinline__ void cp_commit() {
    asm volatile("cp.async.commit_group;" ::: "memory");
}
template<int N> __device__ __forceinline__ void cp_wait() {
    asm volatile("cp.async.wait_group %0;" :: "n"(N) : "memory");
}

// m16n8k8 tf32 mma: D += A(16x8,row) * B(8x8,col).
__device__ __forceinline__ void mma_tf32(float* d, const uint32_t* a, const uint32_t* b) {
    asm volatile(
        "mma.sync.aligned.m16n8k8.row.col.f32.tf32.tf32.f32 "
        "{%0,%1,%2,%3}, {%4,%5,%6,%7}, {%8,%9}, {%0,%1,%2,%3};"
        : "+f"(d[0]), "+f"(d[1]), "+f"(d[2]), "+f"(d[3])
        : "r"(a[0]), "r"(a[1]), "r"(a[2]), "r"(a[3]), "r"(b[0]), "r"(b[1]));
}

// ---------------------------------------------------------------------------
// Kernel r0: elementwise tf32 rounding (float4).
// ---------------------------------------------------------------------------
__global__ void round_tf32(const float4* __restrict__ in, float4* __restrict__ out)
{
    int i = blockIdx.x * blockDim.x + threadIdx.x;
    float4 v = in[i];
    v.x = tf32r(v.x); v.y = tf32r(v.y); v.z = tf32r(v.z); v.w = tf32r(v.w);
    out[i] = v;
}

// ---------------------------------------------------------------------------
// Kernel t0: transpose src[256, ncol] -> dst[ncol, 256], tf32-rounded.
// ---------------------------------------------------------------------------
__global__ void transpose_tf32(const float* __restrict__ src, float* __restrict__ dst, int ncol)
{
    __shared__ float tile[32][33];
    const int bx = blockIdx.x, by = blockIdx.y;
    const int tx = threadIdx.x, ty0 = threadIdx.y;
    #pragma unroll
    for (int j = 0; j < 32; j += 8)
        tile[ty0 + j][tx] = src[(size_t)(by * 32 + ty0 + j) * ncol + bx * 32 + tx];
    __syncthreads();
    #pragma unroll
    for (int j = 0; j < 32; j += 8)
        dst[(size_t)(bx * 32 + ty0 + j) * 256 + by * 32 + tx] = tf32r(tile[tx][ty0 + j]);
}

// ---------------------------------------------------------------------------
// Kernel b0: build bias+mask fragment table.
// out[(h*64+w)*1024 + wm*256 + nt*32 + gid*4 + tig] =
//   { bm(r0,c), bm(r0,c+1), bm(r1,c), bm(r1,c+1) },  r0=wm*16+gid, r1=r0+8,
//   c = nt*8 + tig*2,  bm(r,c) = bias_table[(r-c+63)*8+h] + mask[w][r][c].
// ---------------------------------------------------------------------------
__global__ void bm_build(const float* __restrict__ mask, const float* __restrict__ bt,
                         float4* __restrict__ out)
{
    const int hw = blockIdx.x;             // 0..511
    const int h = hw >> 6, w = hw & 63;
    const int t = threadIdx.x;             // 256
    const int nt = t >> 5, gid = (t >> 2) & 7, tig = t & 3;
    const float* mrow = mask + (size_t)w * 4096;
    float4* op = out + (size_t)hw * 1024 + nt * 32 + gid * 4 + tig;
    const int c = nt * 8 + tig * 2;
    #pragma unroll
    for (int wm = 0; wm < 4; wm++) {
        const int r0 = wm * 16 + gid, r1 = r0 + 8;
        float4 v;
        v.x = bt[(r0 - c + 63) * 8 + h]     + mrow[r0 * 64 + c];
        v.y = bt[(r0 - c + 62) * 8 + h]     + mrow[r0 * 64 + c + 1];
        v.z = bt[(r1 - c + 63) * 8 + h]     + mrow[r1 * 64 + c];
        v.w = bt[(r1 - c + 62) * 8 + h]     + mrow[r1 * 64 + c + 1];
        op[wm * 256] = v;
    }
}

// ---------------------------------------------------------------------------
// Kernel k1/k3: 3-stage cp.async mma.sync tf32 GEMM (unchanged from R9).
// ---------------------------------------------------------------------------
#define BM 128
#define BK 32
#define KP 36
#define STG (BM * KP)
#define NST 3
#define GEMM_SMEM (2 * NST * STG * 4)       // 110592 B

__global__ void __launch_bounds__(256, 2) gemm_tf32(
    const float* __restrict__ A, const float* __restrict__ BT,
    const float* __restrict__ bias, float* __restrict__ C, int ncols)
{
    extern __shared__ float sm[];
    float* sA = sm;
    float* sB = sm + NST * STG;

    const int t = threadIdx.x;
    const int wid = t >> 5, lane = t & 31;
    const int wm = wid & 3, wn = wid >> 2;
    const int gid = lane >> 2, tig = lane & 3;
    const int n0 = blockIdx.x * BM;
    const int m0 = blockIdx.y * BM;
    const uint32_t sAu = smem_u32(sA);
    const uint32_t sBu = smem_u32(sB);

    auto loadAB = [&](int kc, int s) {
        #pragma unroll
        for (int i = 0; i < 4; i++) {
            int f = t + i * 256;
            int r = f >> 3, c4 = f & 7;
            cp_async16(sAu + (uint32_t)(s * STG + r * KP + c4 * 4) * 4,
                       A + (size_t)(m0 + r) * CDIM + kc * BK + c4 * 4);
        }
        #pragma unroll
        for (int i = 0; i < 4; i++) {
            int f = t + i * 256;
            int r = f >> 3, c4 = f & 7;
            cp_async16(sBu + (uint32_t)(s * STG + r * KP + c4 * 4) * 4,
                       BT + (size_t)(n0 + r) * CDIM + kc * BK + c4 * 4);
        }
    };

    float acc[2][8][4];
    #pragma unroll
    for (int mt = 0; mt < 2; mt++)
        #pragma unroll
        for (int nt = 0; nt < 8; nt++)
            #pragma unroll
            for (int e = 0; e < 4; e++) acc[mt][nt][e] = 0.0f;

    loadAB(0, 0); cp_commit();
    loadAB(1, 1); cp_commit();

    #pragma unroll 1
    for (int kc = 0; kc < CDIM / BK; kc++) {
        if (kc < CDIM / BK - 1) cp_wait<1>(); else cp_wait<0>();
        __syncthreads();

        const float* a_s = sA + (kc % NST) * STG;
        const float* b_s = sB + (kc % NST) * STG;
        #pragma unroll
        for (int kk = 0; kk < BK; kk += 8) {
            uint32_t af[2][4], bf[8][2];
            #pragma unroll
            for (int mt = 0; mt < 2; mt++) {
                const float* ap = a_s + (wm * 32 + mt * 16 + gid) * KP + kk + tig;
                af[mt][0] = __float_as_uint(ap[0]);
                af[mt][1] = __float_as_uint(ap[8 * KP]);
                af[mt][2] = __float_as_uint(ap[4]);
                af[mt][3] = __float_as_uint(ap[8 * KP + 4]);
            }
            #pragma unroll
            for (int nt = 0; nt < 8; nt++) {
                const float* bp = b_s + (wn * 64 + nt * 8 + gid) * KP + kk + tig;
                bf[nt][0] = __float_as_uint(bp[0]);
                bf[nt][1] = __float_as_uint(bp[4]);
            }
            #pragma unroll
            for (int mt = 0; mt < 2; mt++)
                #pragma unroll
                for (int nt = 0; nt < 8; nt++)
                    mma_tf32(acc[mt][nt], af[mt], bf[nt]);
        }
        if (kc + 2 < CDIM / BK) { loadAB(kc + 2, (kc + 2) % NST); cp_commit(); }
    }

    #pragma unroll
    for (int mt = 0; mt < 2; mt++) {
        const int r = m0 + wm * 32 + mt * 16 + gid;
        #pragma unroll
        for (int nt = 0; nt < 8; nt++) {
            const int c = n0 + wn * 64 + nt * 8 + tig * 2;
            float b0 = __ldg(bias + c), b1 = __ldg(bias + c + 1);
            float2 v0 = make_float2(acc[mt][nt][0] + b0, acc[mt][nt][1] + b1);
            float2 v1 = make_float2(acc[mt][nt][2] + b0, acc[mt][nt][3] + b1);
            *(float2*)(C + (size_t)r * ncols + c)       = v0;
            *(float2*)(C + (size_t)(r + 8) * ncols + c) = v1;
        }
    }
}

// ---------------------------------------------------------------------------
// Kernel k2: tensor-core attention.
// 2 warp-groups; wg handles head (hp*2+wg), hp=0..3; per-wg named barriers.
// bias+mask via g_BM fragment table (coalesced LDG.128, prefetched).
// V staged naturally [64][36] (no transpose); PV B-frags conflict-free.
// ---------------------------------------------------------------------------
#define QP 36
#define PP 68
#define OFF_Q(wg)   ((wg) * 2304)
#define OFF_K(wg)   (4608 + (wg) * 2304)
#define OFF_V(wg)   (9216 + (wg) * 2304)
#define OFF_P(wg)   (13824 + (wg) * 4352)
#define WATTN_SMEM  ((13824 + 2 * 4352) * 4)   // 90112 B -> 2 CTAs/SM

__global__ void __launch_bounds__(256, 2) wattn(
    const float* __restrict__ qkv, const float4* __restrict__ bmt,
    float* __restrict__ O)
{
    extern __shared__ float sm[];
    const int t = threadIdx.x, wid = t >> 5, lane = t & 31;
    const int wg = wid >> 2, wm = wid & 3;
    const int gid = lane >> 2, tig = lane & 3;
    const int tt = t & 127;
    const int b = blockIdx.x;
    const int barid = 1 + wg;

    float* sQ = sm + OFF_Q(wg);
    float* sK = sm + OFF_K(wg);
    float* sV = sm + OFF_V(wg);
    float* sP = sm + OFF_P(wg);

    const float* base = qkv + (size_t)b * (64 * 768);
    float* og = O + (size_t)b * (64 * 256);

    // Prefetch head hp=0 Q/K into registers.
    float4 pq[4], pk[4];
    #pragma unroll
    for (int i = 0; i < 4; i++) {
        int u = tt + i * 128;
        int n = u >> 3, q = u & 7;
        const float4* rp = (const float4*)(base + n * 768 + wg * 32) + q;
        pq[i] = rp[0];
        pk[i] = rp[64];
    }

    const int r0 = wm * 16 + gid, r1 = r0 + 8;

    for (int hp = 0; hp < 4; hp++) {
        const int h = hp * 2 + wg;
        asm volatile("bar.sync %0, 128;" :: "r"(barid) : "memory");  // prev head reads done

        // Stage Q,K from prefetched regs; V direct (all float4 STS, no transpose).
        #pragma unroll
        for (int i = 0; i < 4; i++) {
            int u = tt + i * 128;
            int n = u >> 3, q = u & 7;
            float4 qa = pq[i];
            qa.x = tf32r(qa.x); qa.y = tf32r(qa.y); qa.z = tf32r(qa.z); qa.w = tf32r(qa.w);
            *(float4*)&sQ[n * QP + q * 4] = qa;
            float4 ka = pk[i];
            ka.x = tf32r(ka.x); ka.y = tf32r(ka.y); ka.z = tf32r(ka.z); ka.w = tf32r(ka.w);
            *(float4*)&sK[n * QP + q * 4] = ka;
            float4 va = *((const float4*)(base + n * 768 + h * 32) + q + 128);
            va.x = tf32r(va.x); va.y = tf32r(va.y); va.z = tf32r(va.z); va.w = tf32r(va.w);
            *(float4*)&sV[n * QP + q * 4] = va;
        }
        asm volatile("bar.sync %0, 128;" :: "r"(barid) : "memory");  // staging visible

        // Prefetch bias+mask fragments for this head (coalesced, from L2).
        float4 bm[8];
        {
            const float4* bmp = bmt + (size_t)((h << 6) | (b & 63)) * 1024
                              + wm * 256 + gid * 4 + tig;
            #pragma unroll
            for (int nt = 0; nt < 8; nt++) bm[nt] = __ldg(bmp + nt * 32);
        }

        // Prefetch next head's Q/K (overlaps with compute below).
        if (hp < 3) {
            #pragma unroll
            for (int i = 0; i < 4; i++) {
                int u = tt + i * 128;
                int n = u >> 3, q = u & 7;
                const float4* rp = (const float4*)(base + n * 768 + (h + 2) * 32) + q;
                pq[i] = rp[0];
                pk[i] = rp[64];
            }
        }

        // S = Q K^T : warp rows wm*16..+15, 64 cols (8 n-tiles).
        float sacc[8][4];
        #pragma unroll
        for (int nt = 0; nt < 8; nt++)
            #pragma unroll
            for (int e = 0; e < 4; e++) sacc[nt][e] = 0.0f;
        #pragma unroll
        for (int kt = 0; kt < 4; kt++) {
            uint32_t af[4];
            const float* ap = sQ + r0 * QP + kt * 8 + tig;
            af[0] = __float_as_uint(ap[0]);
            af[1] = __float_as_uint(ap[8 * QP]);
            af[2] = __float_as_uint(ap[4]);
            af[3] = __float_as_uint(ap[8 * QP + 4]);
            #pragma unroll
            for (int nt = 0; nt < 8; nt++) {
                uint32_t bf[2];
                const float* bp = sK + (nt * 8 + gid) * QP + kt * 8 + tig;
                bf[0] = __float_as_uint(bp[0]);
                bf[1] = __float_as_uint(bp[4]);
                mma_tf32(sacc[nt], af, bf);
            }
        }

        // Softmax rows r0,r1; bias+mask from registers.
        float v0[16], v1[16];
        #pragma unroll
        for (int nt = 0; nt < 8; nt++) {
            v0[nt * 2 + 0] = fmaf(sacc[nt][0], SCALEF, bm[nt].x);
            v0[nt * 2 + 1] = fmaf(sacc[nt][1], SCALEF, bm[nt].y);
            v1[nt * 2 + 0] = fmaf(sacc[nt][2], SCALEF, bm[nt].z);
            v1[nt * 2 + 1] = fmaf(sacc[nt][3], SCALEF, bm[nt].w);
        }
        float mx0 = -1e30f, mx1 = -1e30f;
        #pragma unroll
        for (int i = 0; i < 16; i++) { mx0 = fmaxf(mx0, v0[i]); mx1 = fmaxf(mx1, v1[i]); }
        mx0 = fmaxf(mx0, __shfl_xor_sync(0xffffffffu, mx0, 1));
        mx0 = fmaxf(mx0, __shfl_xor_sync(0xffffffffu, mx0, 2));
        mx1 = fmaxf(mx1, __shfl_xor_sync(0xffffffffu, mx1, 1));
        mx1 = fmaxf(mx1, __shfl_xor_sync(0xffffffffu, mx1, 2));
        float s0 = 0.0f, s1 = 0.0f;
        #pragma unroll
        for (int i = 0; i < 16; i++) {
            v0[i] = __expf(v0[i] - mx0); s0 += v0[i];
            v1[i] = __expf(v1[i] - mx1); s1 += v1[i];
        }
        s0 += __shfl_xor_sync(0xffffffffu, s0, 1);
        s0 += __shfl_xor_sync(0xffffffffu, s0, 2);
        s1 += __shfl_xor_sync(0xffffffffu, s1, 1);
        s1 += __shfl_xor_sync(0xffffffffu, s1, 2);
        const float i0 = 1.0f / s0, i1 = 1.0f / s1;
        #pragma unroll
        for (int nt = 0; nt < 8; nt++) {
            int c = nt * 8 + tig * 2;
            float2 p0 = make_float2(tf32r(v0[nt * 2] * i0), tf32r(v0[nt * 2 + 1] * i0));
            float2 p1 = make_float2(tf32r(v1[nt * 2] * i1), tf32r(v1[nt * 2 + 1] * i1));
            *(float2*)&sP[r0 * PP + c] = p0;
            *(float2*)&sP[r1 * PP + c] = p1;
        }
        __syncwarp();   // P rows are warp-private

        // O = P @ V : 4 n-tiles over head dim 32, k=64.  B-frag from natural V.
        float oacc[4][4];
        #pragma unroll
        for (int nt = 0; nt < 4; nt++)
            #pragma unroll
            for (int e = 0; e < 4; e++) oacc[nt][e] = 0.0f;
        #pragma unroll
        for (int kt = 0; kt < 8; kt++) {
            uint32_t af[4];
            const float* pp = sP + r0 * PP + kt * 8 + tig;
            af[0] = __float_as_uint(pp[0]);
            af[1] = __float_as_uint(pp[8 * PP]);
            af[2] = __float_as_uint(pp[4]);
            af[3] = __float_as_uint(pp[8 * PP + 4]);
            #pragma unroll
            for (int nt = 0; nt < 4; nt++) {
                uint32_t bf[2];
                const float* vp = sV + (kt * 8 + tig) * QP + nt * 8 + gid;
                bf[0] = __float_as_uint(vp[0]);
                bf[1] = __float_as_uint(vp[4 * QP]);
                mma_tf32(oacc[nt], af, bf);
            }
        }
        #pragma unroll
        for (int nt = 0; nt < 4; nt++) {
            const int c = h * 32 + nt * 8 + tig * 2;
            *(float2*)&og[r0 * 256 + c] =
                make_float2(tf32r(oacc[nt][0]), tf32r(oacc[nt][1]));
            *(float2*)&og[r1 * 256 + c] =
                make_float2(tf32r(oacc[nt][2]), tf32r(oacc[nt][3]));
        }
    }
}

// ---------------------------------------------------------------------------
extern "C" void kernel_launch(void* const* d_in, const int* in_sizes, int n_in,
                              void* d_out, int out_size)
{
    const float* x          = (const float*)d_in[0];
    const float* mask       = (const float*)d_in[1];
    const float* wqkv       = (const float*)d_in[2];
    const float* bqkv       = (const float*)d_in[3];
    const float* wproj      = (const float*)d_in[4];
    const float* bproj      = (const float*)d_in[5];
    const float* bias_table = (const float*)d_in[6];
    (void)in_sizes; (void)n_in; (void)out_size;

    cudaFuncSetAttribute(gemm_tf32, cudaFuncAttributeMaxDynamicSharedMemorySize, GEMM_SMEM);
    cudaFuncSetAttribute(wattn, cudaFuncAttributeMaxDynamicSharedMemorySize, WATTN_SMEM);

    float *qkvT, *projT, *qkvS, *oS, *xr;
    float4* bmT;
    cudaGetSymbolAddress((void**)&qkvT,  g_WqkvT);
    cudaGetSymbolAddress((void**)&projT, g_WprojT);
    cudaGetSymbolAddress((void**)&qkvS,  g_QKV);
    cudaGetSymbolAddress((void**)&oS,    g_O);
    cudaGetSymbolAddress((void**)&xr,    g_Xr);
    cudaGetSymbolAddress((void**)&bmT,   g_BM);

    round_tf32<<<65536, 256>>>((const float4*)x, (float4*)xr);
    transpose_tf32<<<dim3(24, 8), dim3(32, 8)>>>(wqkv,  qkvT, 768);
    transpose_tf32<<<dim3(8, 8),  dim3(32, 8)>>>(wproj, projT, 256);
    bm_build<<<512, 256>>>(mask, bias_table, bmT);
    gemm_tf32<<<dim3(6, 2048), 256, GEMM_SMEM>>>(xr, qkvT, bqkv, qkvS, 768);
    wattn<<<NWIN, 256, WATTN_SMEM>>>(qkvS, bmT, oS);
    gemm_tf32<<<dim3(2, 2048), 256, GEMM_SMEM>>>(oS, projT, bproj, (float*)d_out, 256);
}